// round 6
// baseline (speedup 1.0000x reference)
#include <cuda_runtime.h>
#include <cstdint>
#include <cstddef>

#define N0 4096
#define N1 3686
#define N2 2580
#define N3 1548
#define DIMS 64
#define W0 128
#define W1 116
#define W2 81
#define SORTN 4096
#define FULLMASK 0xffffffffu

static __host__ __device__ constexpr size_t alignup(size_t x) { return (x + 255) & ~(size_t)255; }

static constexpr size_t A_G1   = 0;
static constexpr size_t A_G2   = A_G1   + alignup((size_t)N1 * N1 * 4);
static constexpr size_t A_G3   = A_G2   + alignup((size_t)N2 * N2 * 4);
static constexpr size_t A_D0   = A_G3   + alignup((size_t)N3 * N3 * 4);
static constexpr size_t A_D1   = A_D0   + alignup((size_t)N0 * DIMS * 4);
static constexpr size_t A_D2   = A_D1   + alignup((size_t)N1 * DIMS * 4);
static constexpr size_t A_T    = A_D2   + alignup((size_t)N2 * DIMS * 4);
static constexpr size_t A_U    = A_T    + alignup((size_t)N0 * DIMS * 4);
static constexpr size_t A_H    = A_U    + alignup((size_t)N0 * DIMS * 4);
static constexpr size_t A_BITS = A_H    + alignup((size_t)N0 * DIMS * 4);
static constexpr size_t A_SC   = A_BITS + alignup((size_t)N0 * W0 * 4);
static constexpr size_t A_SV   = A_SC   + alignup((size_t)SORTN * 4);
static constexpr size_t A_I0   = A_SV   + alignup((size_t)SORTN * 4);
static constexpr size_t A_I1   = A_I0   + alignup((size_t)SORTN * 4);
static constexpr size_t A_I2   = A_I1   + alignup((size_t)SORTN * 4);
static constexpr size_t A_RS   = A_I2   + alignup((size_t)SORTN * 4);
static constexpr size_t ARENA_BYTES = A_RS + alignup((size_t)SORTN * 4);

__device__ __align__(256) unsigned char g_arena[ARENA_BYTES];

// ---- XLA f32 tanh (rational approx, Eigen ptanh coefficients) ----
__device__ __forceinline__ float xla_tanhf(float x) {
    if (fabsf(x) < 0.0004f) return x;
    float xc = fminf(fmaxf(x, -7.90531110763549805f), 7.90531110763549805f);
    float x2 = xc * xc;
    float p = -2.76076847742355e-16f;
    p = fmaf(p, x2, 2.00018790482477e-13f);
    p = fmaf(p, x2, -8.60467152213735e-11f);
    p = fmaf(p, x2, 5.12229709037114e-08f);
    p = fmaf(p, x2, 1.48572235717979e-05f);
    p = fmaf(p, x2, 6.37261928875436e-04f);
    p = fmaf(p, x2, 4.89352455891786e-03f);
    float num = xc * p;
    float q = 1.19825839466702e-06f;
    q = fmaf(q, x2, 1.18534705686654e-04f);
    q = fmaf(q, x2, 2.26843463243900e-03f);
    q = fmaf(q, x2, 4.89352518554385e-03f);
    return num / q;
}

// XLA logistic_expander: sigmoid(x) = 0.5 + 0.5 * tanh(0.5 * x)
// (0.5*x and 0.5*T are exact scalings; fmaf == mul+add here)
__device__ __forceinline__ float xla_sigmoidf(float x) {
    return fmaf(0.5f, xla_tanhf(0.5f * x), 0.5f);
}

// ---- t = g @ h, dense smem-tiled; per-element k-ascending FFMA from 0 ----
__global__ void k_gemm(const float* __restrict__ g, const float* __restrict__ h,
                       float* __restrict__ t, int n) {
    __shared__ float gs[64][65];
    __shared__ float hs[64][64];
    int tid = threadIdx.x;
    int tx = tid & 15, ty = tid >> 4;
    int tx4 = tx * 4, ty4 = ty * 4;
    int rbase = blockIdx.x * 64;
    float acc[4][4];
#pragma unroll
    for (int i = 0; i < 4; ++i)
#pragma unroll
        for (int j = 0; j < 4; ++j) acc[i][j] = 0.f;

    for (int kb = 0; kb < n; kb += 64) {
        for (int i2 = tid; i2 < 4096; i2 += 256) {
            int rr = i2 >> 6, cc = i2 & 63;
            int gr = rbase + rr, gc = kb + cc;
            gs[rr][cc] = (gr < n && gc < n) ? g[(size_t)gr * n + gc] : 0.f;
            int hr = kb + rr;
            hs[rr][cc] = (hr < n) ? h[(size_t)hr * DIMS + cc] : 0.f;
        }
        __syncthreads();
#pragma unroll 8
        for (int kk = 0; kk < 64; ++kk) {
            float a0 = gs[ty4 + 0][kk], a1 = gs[ty4 + 1][kk];
            float a2 = gs[ty4 + 2][kk], a3 = gs[ty4 + 3][kk];
            float b0 = hs[kk][tx4 + 0], b1 = hs[kk][tx4 + 1];
            float b2 = hs[kk][tx4 + 2], b3 = hs[kk][tx4 + 3];
            acc[0][0] = fmaf(a0, b0, acc[0][0]); acc[0][1] = fmaf(a0, b1, acc[0][1]);
            acc[0][2] = fmaf(a0, b2, acc[0][2]); acc[0][3] = fmaf(a0, b3, acc[0][3]);
            acc[1][0] = fmaf(a1, b0, acc[1][0]); acc[1][1] = fmaf(a1, b1, acc[1][1]);
            acc[1][2] = fmaf(a1, b2, acc[1][2]); acc[1][3] = fmaf(a1, b3, acc[1][3]);
            acc[2][0] = fmaf(a2, b0, acc[2][0]); acc[2][1] = fmaf(a2, b1, acc[2][1]);
            acc[2][2] = fmaf(a2, b2, acc[2][2]); acc[2][3] = fmaf(a2, b3, acc[2][3]);
            acc[3][0] = fmaf(a3, b0, acc[3][0]); acc[3][1] = fmaf(a3, b1, acc[3][1]);
            acc[3][2] = fmaf(a3, b2, acc[3][2]); acc[3][3] = fmaf(a3, b3, acc[3][3]);
        }
        __syncthreads();
    }
#pragma unroll
    for (int i = 0; i < 4; ++i) {
        int r = rbase + ty4 + i;
        if (r < n) {
#pragma unroll
            for (int j = 0; j < 4; ++j)
                t[(size_t)r * DIMS + tx4 + j] = acc[i][j];
        }
    }
}

// ---- out = relu((t @ W) + b) [+ res]; acc from 0, +b AFTER sum (XLA order) ----
__global__ void k_proj(const float* __restrict__ t, const float* __restrict__ Wm,
                       const float* __restrict__ b, const float* __restrict__ res,
                       float* __restrict__ out, int n) {
    __shared__ float Ws[64 * 64];
    __shared__ float Ts[4 * 64];
    int tid = threadIdx.x;
    int d = tid & 63;
    int r4 = tid >> 6;
    int row = blockIdx.x * 4 + r4;
    for (int i = tid; i < 4096; i += 256) Ws[i] = Wm[i];
    {
        int rr = blockIdx.x * 4 + (tid >> 6);
        Ts[tid] = (rr < n) ? t[(size_t)rr * DIMS + (tid & 63)] : 0.f;
    }
    __syncthreads();
    if (row < n) {
        float acc = 0.f;
#pragma unroll
        for (int k = 0; k < 64; ++k)
            acc = fmaf(Ts[r4 * 64 + k], Ws[k * 64 + d], acc);
        acc = acc + b[d];
        acc = fmaxf(acc, 0.f);
        if (res) acc += res[(size_t)row * DIMS + d];
        out[(size_t)row * DIMS + d] = acc;
    }
}

// ---- scores = xla_sigmoid(h @ pw + pb); strided-2 fma + butterfly reduce ----
__global__ void k_scores(const float* __restrict__ h, const float* __restrict__ pw,
                         const float* __restrict__ pb, float* __restrict__ sc, int n) {
    int warp = (int)((blockIdx.x * (unsigned)blockDim.x + threadIdx.x) >> 5);
    int lane = threadIdx.x & 31;
    if (warp >= n) return;
    float acc = h[(size_t)warp * DIMS + lane] * pw[lane];
    acc = fmaf(h[(size_t)warp * DIMS + lane + 32], pw[lane + 32], acc);
#pragma unroll
    for (int off = 16; off > 0; off >>= 1) acc += __shfl_xor_sync(FULLMASK, acc, off);
    if (lane == 0) sc[warp] = xla_sigmoidf(acc + pb[0]);
}

// ---- exact bitonic top-k: (score desc, idx asc) via packed u64 keys ----
__global__ void k_sort(const float* __restrict__ sc, int n, int k,
                       int* __restrict__ idx_out, float* __restrict__ vals_out) {
    __shared__ unsigned long long ks[SORTN];
    int tid = threadIdx.x;
    for (int j = tid; j < SORTN; j += 1024) {
        if (j < n) {
            unsigned fb = __float_as_uint(sc[j]);
            ks[j] = ((unsigned long long)(~fb) << 32) | (unsigned)j;
        } else {
            ks[j] = 0xFFFFFFFFFFFFFFFFull;
        }
    }
    __syncthreads();
    for (int size = 2; size <= SORTN; size <<= 1) {
        for (int stride = size >> 1; stride > 0; stride >>= 1) {
            for (int t2 = tid; t2 < SORTN / 2; t2 += 1024) {
                int i = 2 * t2 - (t2 & (stride - 1));
                int j = i + stride;
                unsigned long long ki = ks[i], kj = ks[j];
                bool asc = ((i & size) == 0);
                bool sw = asc ? (ki > kj) : (ki < kj);
                if (sw) { ks[i] = kj; ks[j] = ki; }
            }
            __syncthreads();
        }
    }
    for (int j = tid; j < k; j += 1024) {
        unsigned long long key = ks[j];
        idx_out[j] = (int)(key & 0xFFFFFFFFull);
        vals_out[j] = __uint_as_float(~(unsigned)(key >> 32));
    }
}

__global__ void k_gather(const float* __restrict__ hsrc, const int* __restrict__ idx,
                         const float* __restrict__ vals, float* __restrict__ hout) {
    int b = blockIdx.x, t = threadIdx.x;
    hout[(size_t)b * DIMS + t] = hsrc[(size_t)idx[b] * DIMS + t] * vals[b];
}

// ---- bit-pack (g != 0) rows gathered by idx ----
__global__ void k_pack(const float* __restrict__ g, const int* __restrict__ idx,
                       unsigned* __restrict__ bits, int n, int rows, int Wl) {
    int gw = (int)((blockIdx.x * (unsigned)blockDim.x + threadIdx.x) >> 5);
    int lane = threadIdx.x & 31;
    if (gw >= rows * Wl) return;
    int r = gw / Wl, w = gw - r * Wl;
    int src = idx ? idx[r] : r;
    int c = w * 32 + lane;
    float v = (c < n) ? g[(size_t)src * n + c] : 0.f;
    unsigned m = __ballot_sync(FULLMASK, v != 0.f);
    if (lane == 0) bits[(size_t)r * Wl + w] = m;
}

// ---- pairwise 2-hop: C[i,j] = packed-row overlap (symmetric ug), early exit ----
__global__ void k_pair(const unsigned* __restrict__ A, int kk, int Wl,
                       float* __restrict__ gout, float* __restrict__ rowsum) {
    __shared__ unsigned As[64 * 9];
    __shared__ unsigned Bs[64 * 9];
    __shared__ float rc[64];
    int tid = threadIdx.x;
    int tx = tid & 15, ty = tid >> 4;
    int rbase = blockIdx.y * 64, cbase = blockIdx.x * 64;
    int ty4 = ty * 4, tx4 = tx * 4;
    if (tid < 64) rc[tid] = 0.f;

    unsigned acc[4][4];
#pragma unroll
    for (int i = 0; i < 4; ++i)
#pragma unroll
        for (int j = 0; j < 4; ++j) {
            bool valid = (rbase + ty4 + i < kk) && (cbase + tx4 + j < kk);
            acc[i][j] = valid ? 0u : 1u;
        }

    bool done = false;
    for (int ch = 0; ch < Wl; ch += 8) {
        for (int i2 = tid; i2 < 512; i2 += 256) {
            int rr = i2 >> 3, ww = i2 & 7;
            int gw = ch + ww;
            int grow = rbase + rr;
            int gcol = cbase + rr;
            As[rr * 9 + ww] = (grow < kk && gw < Wl) ? A[(size_t)grow * Wl + gw] : 0u;
            Bs[rr * 9 + ww] = (gcol < kk && gw < Wl) ? A[(size_t)gcol * Wl + gw] : 0u;
        }
        __syncthreads();
        if (!done) {
#pragma unroll
            for (int w = 0; w < 8; ++w) {
                unsigned a0 = As[(ty4 + 0) * 9 + w];
                unsigned a1 = As[(ty4 + 1) * 9 + w];
                unsigned a2 = As[(ty4 + 2) * 9 + w];
                unsigned a3 = As[(ty4 + 3) * 9 + w];
                unsigned b0 = Bs[(tx4 + 0) * 9 + w];
                unsigned b1 = Bs[(tx4 + 1) * 9 + w];
                unsigned b2 = Bs[(tx4 + 2) * 9 + w];
                unsigned b3 = Bs[(tx4 + 3) * 9 + w];
                acc[0][0] |= a0 & b0; acc[0][1] |= a0 & b1; acc[0][2] |= a0 & b2; acc[0][3] |= a0 & b3;
                acc[1][0] |= a1 & b0; acc[1][1] |= a1 & b1; acc[1][2] |= a1 & b2; acc[1][3] |= a1 & b3;
                acc[2][0] |= a2 & b0; acc[2][1] |= a2 & b1; acc[2][2] |= a2 & b2; acc[2][3] |= a2 & b3;
                acc[3][0] |= a3 & b0; acc[3][1] |= a3 & b1; acc[3][2] |= a3 & b2; acc[3][3] |= a3 & b3;
            }
            bool d = true;
#pragma unroll
            for (int i = 0; i < 4; ++i)
#pragma unroll
                for (int j = 0; j < 4; ++j) d = d && (acc[i][j] != 0u);
            done = d;
        }
        if (__syncthreads_and(done ? 1 : 0)) break;
    }

#pragma unroll
    for (int i = 0; i < 4; ++i) {
        int r = rbase + ty4 + i;
        int cnt = 0;
        if (r < kk) {
#pragma unroll
            for (int j = 0; j < 4; ++j) {
                int c = cbase + tx4 + j;
                if (c < kk) {
                    gout[(size_t)r * kk + c] = acc[i][j] ? 1.f : 0.f;
                    cnt += acc[i][j] ? 1 : 0;
                }
            }
        }
        if (cnt) atomicAdd(&rc[ty4 + i], (float)cnt);
    }
    __syncthreads();
    if (tid < 64) {
        int r = rbase + tid;
        if (r < kk && rc[tid] != 0.f) atomicAdd(&rowsum[r], rc[tid]);
    }
}

__global__ void k_scale(float* __restrict__ g, const float* __restrict__ rowsum, int kk) {
    int row = blockIdx.y;
    int c = blockIdx.x * 256 + threadIdx.x;
    if (c < kk) g[(size_t)row * kk + c] *= (1.0f / rowsum[row]);
}

__global__ void k_zero(float* __restrict__ p, int n) {
    int i = blockIdx.x * 256 + threadIdx.x;
    if (i < n) p[i] = 0.f;
}

__global__ void k_scatter(const float* __restrict__ hsrc, const int* __restrict__ idx,
                          float* __restrict__ u) {
    int b = blockIdx.x, t = threadIdx.x;
    u[(size_t)idx[b] * DIMS + t] = hsrc[(size_t)b * DIMS + t];
}

__global__ void k_add(const float* __restrict__ a, const float* __restrict__ b,
                      float* __restrict__ o, int n) {
    int i = blockIdx.x * 256 + threadIdx.x;
    if (i < n) o[i] = a[i] + b[i];
}

extern "C" void kernel_launch(void* const* d_in, const int* in_sizes, int n_in,
                              void* d_out, int out_size) {
    (void)in_sizes; (void)n_in; (void)out_size;
    const float* g0   = (const float*)d_in[0];
    const float* h_in = (const float*)d_in[1];
    const float* dW   = (const float*)d_in[2];
    const float* db   = (const float*)d_in[3];
    const float* uW   = (const float*)d_in[4];
    const float* ub   = (const float*)d_in[5];
    const float* pW   = (const float*)d_in[6];
    const float* pb   = (const float*)d_in[7];
    const float* bW   = (const float*)d_in[8];
    const float* bb   = (const float*)d_in[9];
    float* out = (float*)d_out;
    float* out0 = out;                               // [N2,64]
    float* out1 = out + (size_t)N2 * DIMS;           // [N1,64]
    float* out2 = out1 + (size_t)N1 * DIMS;          // [N0,64]
    float* out3 = out2 + (size_t)N0 * DIMS;          // [N0,64]

    void* basep = nullptr;
    cudaGetSymbolAddress(&basep, g_arena);
    char* base = (char*)basep;
    float*    G1   = (float*)(base + A_G1);
    float*    G2   = (float*)(base + A_G2);
    float*    G3   = (float*)(base + A_G3);
    float*    D0b  = (float*)(base + A_D0);
    float*    D1b  = (float*)(base + A_D1);
    float*    D2b  = (float*)(base + A_D2);
    float*    T    = (float*)(base + A_T);
    float*    U    = (float*)(base + A_U);
    float*    Hb   = (float*)(base + A_H);
    unsigned* BITS = (unsigned*)(base + A_BITS);
    float*    SC   = (float*)(base + A_SC);
    float*    SV   = (float*)(base + A_SV);
    int*      I0   = (int*)(base + A_I0);
    int*      I1   = (int*)(base + A_I1);
    int*      I2   = (int*)(base + A_I2);
    float*    RS   = (float*)(base + A_RS);

    // ---------------- down level 0 ----------------
    k_gemm<<<(N0 + 63) / 64, 256>>>(g0, h_in, T, N0);
    k_proj<<<(N0 + 3) / 4, 256>>>(T, dW, db, nullptr, D0b, N0);
    k_scores<<<(N0 + 7) / 8, 256>>>(D0b, pW, pb, SC, N0);
    k_sort<<<1, 1024>>>(SC, N0, N1, I0, SV);
    k_gather<<<N1, 64>>>(D0b, I0, SV, Hb);
    k_pack<<<(N1 * W0 + 7) / 8, 256>>>(g0, I0, BITS, N0, N1, W0);
    k_zero<<<(N1 + 255) / 256, 256>>>(RS, N1);
    {
        dim3 grid((N1 + 63) / 64, (N1 + 63) / 64);
        k_pair<<<grid, 256>>>(BITS, N1, W0, G1, RS);
        dim3 sg((N1 + 255) / 256, N1);
        k_scale<<<sg, 256>>>(G1, RS, N1);
    }

    // ---------------- down level 1 ----------------
    k_gemm<<<(N1 + 63) / 64, 256>>>(G1, Hb, T, N1);
    k_proj<<<(N1 + 3) / 4, 256>>>(T, dW + 4096, db + 64, nullptr, D1b, N1);
    k_scores<<<(N1 + 7) / 8, 256>>>(D1b, pW + 64, pb + 1, SC, N1);
    k_sort<<<1, 1024>>>(SC, N1, N2, I1, SV);
    k_gather<<<N2, 64>>>(D1b, I1, SV, Hb);
    k_pack<<<(N2 * W1 + 7) / 8, 256>>>(G1, I1, BITS, N1, N2, W1);
    k_zero<<<(N2 + 255) / 256, 256>>>(RS, N2);
    {
        dim3 grid((N2 + 63) / 64, (N2 + 63) / 64);
        k_pair<<<grid, 256>>>(BITS, N2, W1, G2, RS);
        dim3 sg((N2 + 255) / 256, N2);
        k_scale<<<sg, 256>>>(G2, RS, N2);
    }

    // ---------------- down level 2 ----------------
    k_gemm<<<(N2 + 63) / 64, 256>>>(G2, Hb, T, N2);
    k_proj<<<(N2 + 3) / 4, 256>>>(T, dW + 8192, db + 128, nullptr, D2b, N2);
    k_scores<<<(N2 + 7) / 8, 256>>>(D2b, pW + 128, pb + 2, SC, N2);
    k_sort<<<1, 1024>>>(SC, N2, N3, I2, SV);
    k_gather<<<N3, 64>>>(D2b, I2, SV, Hb);
    k_pack<<<(N3 * W2 + 7) / 8, 256>>>(G2, I2, BITS, N2, N3, W2);
    k_zero<<<(N3 + 255) / 256, 256>>>(RS, N3);
    {
        dim3 grid((N3 + 63) / 64, (N3 + 63) / 64);
        k_pair<<<grid, 256>>>(BITS, N3, W2, G3, RS);
        dim3 sg((N3 + 255) / 256, N3);
        k_scale<<<sg, 256>>>(G3, RS, N3);
    }

    // ---------------- bottom ----------------
    k_gemm<<<(N3 + 63) / 64, 256>>>(G3, Hb, T, N3);
    k_proj<<<(N3 + 3) / 4, 256>>>(T, bW, bb, nullptr, Hb, N3);

    // ---------------- up level 0 (uses G2, I2) ----------------
    k_zero<<<(N2 * DIMS + 255) / 256, 256>>>(U, N2 * DIMS);
    k_scatter<<<N3, 64>>>(Hb, I2, U);
    k_gemm<<<(N2 + 63) / 64, 256>>>(G2, U, T, N2);
    k_proj<<<(N2 + 3) / 4, 256>>>(T, uW, ub, D2b, out0, N2);

    // ---------------- up level 1 (uses G1, I1) ----------------
    k_zero<<<(N1 * DIMS + 255) / 256, 256>>>(U, N1 * DIMS);
    k_scatter<<<N2, 64>>>(out0, I1, U);
    k_gemm<<<(N1 + 63) / 64, 256>>>(G1, U, T, N1);
    k_proj<<<(N1 + 3) / 4, 256>>>(T, uW + 4096, ub + 64, D1b, out1, N1);

    // ---------------- up level 2 (uses g0, I0) ----------------
    k_zero<<<(N0 * DIMS + 255) / 256, 256>>>(U, N0 * DIMS);
    k_scatter<<<N1, 64>>>(out1, I0, U);
    k_gemm<<<(N0 + 63) / 64, 256>>>(g0, U, T, N0);
    k_proj<<<(N0 + 3) / 4, 256>>>(T, uW + 8192, ub + 128, D0b, out2, N0);

    // ---------------- final residual ----------------
    k_add<<<(N0 * DIMS + 255) / 256, 256>>>(out2, h_in, out3, N0 * DIMS);
}

// round 7
// speedup vs baseline: 1.6249x; 1.6249x over previous
#include <cuda_runtime.h>
#include <cstdint>
#include <cstddef>

#define N0 4096
#define N1 3686
#define N2 2580
#define N3 1548
#define DIMS 64
#define W0 128   /* ceil(N0/32) */
#define W1 116   /* ceil(N1/32) */
#define W2 81    /* ceil(N2/32) */
#define W3 49    /* ceil(N3/32) */
#define SORTN 4096
#define FULLMASK 0xffffffffu

static __host__ __device__ constexpr size_t alignup(size_t x) { return (x + 255) & ~(size_t)255; }

static constexpr size_t A_CB1  = 0;
static constexpr size_t A_CB2  = A_CB1  + alignup((size_t)N1 * W1 * 4);
static constexpr size_t A_CB3  = A_CB2  + alignup((size_t)N2 * W2 * 4);
static constexpr size_t A_BITS = A_CB3  + alignup((size_t)N3 * W3 * 4);
static constexpr size_t A_T    = A_BITS + alignup((size_t)N1 * W0 * 4);
static constexpr size_t A_U    = A_T    + alignup((size_t)N0 * DIMS * 4);
static constexpr size_t A_H    = A_U    + alignup((size_t)N0 * DIMS * 4);
static constexpr size_t A_D0   = A_H    + alignup((size_t)N0 * DIMS * 4);
static constexpr size_t A_D1   = A_D0   + alignup((size_t)N0 * DIMS * 4);
static constexpr size_t A_D2   = A_D1   + alignup((size_t)N1 * DIMS * 4);
static constexpr size_t A_SC   = A_D2   + alignup((size_t)N2 * DIMS * 4);
static constexpr size_t A_SV   = A_SC   + alignup((size_t)SORTN * 4);
static constexpr size_t A_I0   = A_SV   + alignup((size_t)SORTN * 4);
static constexpr size_t A_I1   = A_I0   + alignup((size_t)SORTN * 4);
static constexpr size_t A_I2   = A_I1   + alignup((size_t)SORTN * 4);
static constexpr size_t A_RS1  = A_I2   + alignup((size_t)SORTN * 4);
static constexpr size_t A_RS2  = A_RS1  + alignup((size_t)SORTN * 4);
static constexpr size_t A_RS3  = A_RS2  + alignup((size_t)SORTN * 4);
static constexpr size_t ARENA_BYTES = A_RS3 + alignup((size_t)SORTN * 4);

__device__ __align__(256) unsigned char g_arena[ARENA_BYTES];

// ---- XLA f32 tanh (Eigen ptanh) + logistic expansion ----
__device__ __forceinline__ float xla_tanhf(float x) {
    if (fabsf(x) < 0.0004f) return x;
    float xc = fminf(fmaxf(x, -7.90531110763549805f), 7.90531110763549805f);
    float x2 = xc * xc;
    float p = -2.76076847742355e-16f;
    p = fmaf(p, x2, 2.00018790482477e-13f);
    p = fmaf(p, x2, -8.60467152213735e-11f);
    p = fmaf(p, x2, 5.12229709037114e-08f);
    p = fmaf(p, x2, 1.48572235717979e-05f);
    p = fmaf(p, x2, 6.37261928875436e-04f);
    p = fmaf(p, x2, 4.89352455891786e-03f);
    float num = xc * p;
    float q = 1.19825839466702e-06f;
    q = fmaf(q, x2, 1.18534705686654e-04f);
    q = fmaf(q, x2, 2.26843463243900e-03f);
    q = fmaf(q, x2, 4.89352518554385e-03f);
    return num / q;
}
__device__ __forceinline__ float xla_sigmoidf(float x) {
    return fmaf(0.5f, xla_tanhf(0.5f * x), 0.5f);
}

// ---- t = g @ h, ballot-compacted sparse scan over float g (bit-exact
//      zero-skip, k-ascending; empirically ≡ dense gemm on these inputs) ----
__global__ void k_spmm_f(const float* __restrict__ g, const float* __restrict__ h,
                         float* __restrict__ t, int n) {
    int warp = (int)((blockIdx.x * (unsigned)blockDim.x + threadIdx.x) >> 5);
    int lane = threadIdx.x & 31;
    if (warp >= n) return;
    const float* row = g + (size_t)warp * n;
    float a0 = 0.f, a1 = 0.f;
    for (int b = 0; b < n; b += 32) {
        int c = b + lane;
        float v = (c < n) ? row[c] : 0.f;
        unsigned m = __ballot_sync(FULLMASK, v != 0.f);
        while (m) {
            int src = __ffs(m) - 1;
            m &= m - 1;
            float val = __shfl_sync(FULLMASK, v, src);
            const float* hp = h + (size_t)(b + src) * DIMS;
            a0 = fmaf(val, hp[lane], a0);
            a1 = fmaf(val, hp[lane + 32], a1);
        }
    }
    t[(size_t)warp * DIMS + lane]      = a0;
    t[(size_t)warp * DIMS + lane + 32] = a1;
}

// ---- t = G @ h where G = bits * (1/RS[row]); warp per row, ffs ascending ----
__global__ void k_spmm_bits(const unsigned* __restrict__ CB, const float* __restrict__ RS,
                            const float* __restrict__ h, float* __restrict__ t,
                            int n, int Wl) {
    int warp = (int)((blockIdx.x * (unsigned)blockDim.x + threadIdx.x) >> 5);
    int lane = threadIdx.x & 31;
    if (warp >= n) return;
    const unsigned* row = CB + (size_t)warp * Wl;
    float inv = 1.0f / RS[warp];
    float a0 = 0.f, a1 = 0.f;
    for (int wb = 0; wb < Wl; wb += 32) {
        unsigned myw = (wb + lane < Wl) ? row[wb + lane] : 0u;
        unsigned any = __ballot_sync(FULLMASK, myw != 0u);
        while (any) {
            int s = __ffs(any) - 1;
            any &= any - 1;
            unsigned word = __shfl_sync(FULLMASK, myw, s);
            int cb = (wb + s) << 5;
            while (word) {
                int c = cb + __ffs(word) - 1;
                word &= word - 1;
                const float* hp = h + (size_t)c * DIMS;
                a0 = fmaf(inv, hp[lane], a0);
                a1 = fmaf(inv, hp[lane + 32], a1);
            }
        }
    }
    t[(size_t)warp * DIMS + lane]      = a0;
    t[(size_t)warp * DIMS + lane + 32] = a1;
}

// ---- t = G @ h, smem-tiled dense sweep with G expanded from bits.
//      16-row tiles for occupancy; per-element FMA order = k ascending ----
__global__ void k_gemm_bits(const unsigned* __restrict__ CB, const float* __restrict__ RS,
                            const float* __restrict__ h, float* __restrict__ t,
                            int n, int Wl) {
    __shared__ float gs[16][65];
    __shared__ float hs[64][64];
    __shared__ float invs[16];
    int tid = threadIdx.x;
    int tx = tid & 15, ty = tid >> 4;
    int tx4 = tx * 4;
    int rbase = blockIdx.x * 16;
    if (tid < 16) {
        int r = rbase + tid;
        invs[tid] = (r < n) ? 1.0f / RS[r] : 0.f;
    }
    __syncthreads();
    float acc[4] = {0.f, 0.f, 0.f, 0.f};

    for (int kb = 0; kb < n; kb += 64) {
        for (int i2 = tid; i2 < 1024; i2 += 256) {
            int rr = i2 >> 6, cc = i2 & 63;
            int gr = rbase + rr, gc = kb + cc;
            bool bit = (gr < n && gc < n) &&
                       ((CB[(size_t)gr * Wl + (gc >> 5)] >> (gc & 31)) & 1u);
            gs[rr][cc] = bit ? invs[rr] : 0.f;
        }
        for (int i2 = tid; i2 < 4096; i2 += 256) {
            int rr = i2 >> 6, cc = i2 & 63;
            int hr = kb + rr;
            hs[rr][cc] = (hr < n) ? h[(size_t)hr * DIMS + cc] : 0.f;
        }
        __syncthreads();
#pragma unroll 8
        for (int kk = 0; kk < 64; ++kk) {
            float a = gs[ty][kk];
            acc[0] = fmaf(a, hs[kk][tx4 + 0], acc[0]);
            acc[1] = fmaf(a, hs[kk][tx4 + 1], acc[1]);
            acc[2] = fmaf(a, hs[kk][tx4 + 2], acc[2]);
            acc[3] = fmaf(a, hs[kk][tx4 + 3], acc[3]);
        }
        __syncthreads();
    }
    int r = rbase + ty;
    if (r < n) {
#pragma unroll
        for (int j = 0; j < 4; ++j)
            t[(size_t)r * DIMS + tx4 + j] = acc[j];
    }
}

// ---- out = relu((t @ W) + b) [+ res] ----
__global__ void k_proj(const float* __restrict__ t, const float* __restrict__ Wm,
                       const float* __restrict__ b, const float* __restrict__ res,
                       float* __restrict__ out, int n) {
    __shared__ float Ws[64 * 64];
    __shared__ float Ts[4 * 64];
    int tid = threadIdx.x;
    int d = tid & 63;
    int r4 = tid >> 6;
    int row = blockIdx.x * 4 + r4;
    for (int i = tid; i < 4096; i += 256) Ws[i] = Wm[i];
    {
        int rr = blockIdx.x * 4 + (tid >> 6);
        Ts[tid] = (rr < n) ? t[(size_t)rr * DIMS + (tid & 63)] : 0.f;
    }
    __syncthreads();
    if (row < n) {
        float acc = 0.f;
#pragma unroll
        for (int k = 0; k < 64; ++k)
            acc = fmaf(Ts[r4 * 64 + k], Ws[k * 64 + d], acc);
        acc = acc + b[d];
        acc = fmaxf(acc, 0.f);
        if (res) acc += res[(size_t)row * DIMS + d];
        out[(size_t)row * DIMS + d] = acc;
    }
}

// ---- scores = xla_sigmoid(h @ pw + pb) ----
__global__ void k_scores(const float* __restrict__ h, const float* __restrict__ pw,
                         const float* __restrict__ pb, float* __restrict__ sc, int n) {
    int warp = (int)((blockIdx.x * (unsigned)blockDim.x + threadIdx.x) >> 5);
    int lane = threadIdx.x & 31;
    if (warp >= n) return;
    float acc = h[(size_t)warp * DIMS + lane] * pw[lane];
    acc = fmaf(h[(size_t)warp * DIMS + lane + 32], pw[lane + 32], acc);
#pragma unroll
    for (int off = 16; off > 0; off >>= 1) acc += __shfl_xor_sync(FULLMASK, acc, off);
    if (lane == 0) sc[warp] = xla_sigmoidf(acc + pb[0]);
}

// ---- exact bitonic top-k: (score desc, idx asc) via packed u64 keys ----
__global__ void k_sort(const float* __restrict__ sc, int n, int k,
                       int* __restrict__ idx_out, float* __restrict__ vals_out) {
    __shared__ unsigned long long ks[SORTN];
    int tid = threadIdx.x;
    for (int j = tid; j < SORTN; j += 1024) {
        if (j < n) {
            unsigned fb = __float_as_uint(sc[j]);
            ks[j] = ((unsigned long long)(~fb) << 32) | (unsigned)j;
        } else {
            ks[j] = 0xFFFFFFFFFFFFFFFFull;
        }
    }
    __syncthreads();
    for (int size = 2; size <= SORTN; size <<= 1) {
        for (int stride = size >> 1; stride > 0; stride >>= 1) {
            for (int t2 = tid; t2 < SORTN / 2; t2 += 1024) {
                int i = 2 * t2 - (t2 & (stride - 1));
                int j = i + stride;
                unsigned long long ki = ks[i], kj = ks[j];
                bool asc = ((i & size) == 0);
                bool sw = asc ? (ki > kj) : (ki < kj);
                if (sw) { ks[i] = kj; ks[j] = ki; }
            }
            __syncthreads();
        }
    }
    for (int j = tid; j < k; j += 1024) {
        unsigned long long key = ks[j];
        idx_out[j] = (int)(key & 0xFFFFFFFFull);
        vals_out[j] = __uint_as_float(~(unsigned)(key >> 32));
    }
}

__global__ void k_gather(const float* __restrict__ hsrc, const int* __restrict__ idx,
                         const float* __restrict__ vals, float* __restrict__ hout) {
    int b = blockIdx.x, t = threadIdx.x;
    hout[(size_t)b * DIMS + t] = hsrc[(size_t)idx[b] * DIMS + t] * vals[b];
}

// ---- bit-pack (g != 0) float rows gathered by idx (level 0 only) ----
__global__ void k_pack(const float* __restrict__ g, const int* __restrict__ idx,
                       unsigned* __restrict__ bits, int n, int rows, int Wl) {
    int gw = (int)((blockIdx.x * (unsigned)blockDim.x + threadIdx.x) >> 5);
    int lane = threadIdx.x & 31;
    if (gw >= rows * Wl) return;
    int r = gw / Wl, w = gw - r * Wl;
    int src = idx ? idx[r] : r;
    int c = w * 32 + lane;
    float v = (c < n) ? g[(size_t)src * n + c] : 0.f;
    unsigned m = __ballot_sync(FULLMASK, v != 0.f);
    if (lane == 0) bits[(size_t)r * Wl + w] = m;
}

// ---- gather packed bit rows by idx ----
__global__ void k_packb(const unsigned* __restrict__ src, const int* __restrict__ idx,
                        unsigned* __restrict__ dst, int rows, int Wl) {
    int i = blockIdx.x * 256 + threadIdx.x;
    if (i >= rows * Wl) return;
    int r = i / Wl, w = i - r * Wl;
    dst[(size_t)r * Wl + w] = src[(size_t)idx[r] * Wl + w];
}

// ---- pairwise 2-hop with PACKED output: CB bits + rowsum (float counts) ----
__global__ void k_pairb(const unsigned* __restrict__ A, int kk, int Wl, int Wout,
                        unsigned* __restrict__ CB, float* __restrict__ rowsum) {
    __shared__ unsigned As[64 * 9];
    __shared__ unsigned Bs[64 * 9];
    __shared__ unsigned obits[128];
    __shared__ float rc[64];
    int tid = threadIdx.x;
    int tx = tid & 15, ty = tid >> 4;
    int rbase = blockIdx.y * 64, cbase = blockIdx.x * 64;
    int ty4 = ty * 4, tx4 = tx * 4;
    if (tid < 64) rc[tid] = 0.f;
    if (tid < 128) obits[tid] = 0u;

    unsigned acc[4][4];
#pragma unroll
    for (int i = 0; i < 4; ++i)
#pragma unroll
        for (int j = 0; j < 4; ++j) {
            bool valid = (rbase + ty4 + i < kk) && (cbase + tx4 + j < kk);
            acc[i][j] = valid ? 0u : 1u;
        }

    bool done = false;
    for (int ch = 0; ch < Wl; ch += 8) {
        for (int i2 = tid; i2 < 512; i2 += 256) {
            int rr = i2 >> 3, ww = i2 & 7;
            int gw = ch + ww;
            int grow = rbase + rr;
            int gcol = cbase + rr;
            As[rr * 9 + ww] = (grow < kk && gw < Wl) ? A[(size_t)grow * Wl + gw] : 0u;
            Bs[rr * 9 + ww] = (gcol < kk && gw < Wl) ? A[(size_t)gcol * Wl + gw] : 0u;
        }
        __syncthreads();
        if (!done) {
#pragma unroll
            for (int w = 0; w < 8; ++w) {
                unsigned a0 = As[(ty4 + 0) * 9 + w];
                unsigned a1 = As[(ty4 + 1) * 9 + w];
                unsigned a2 = As[(ty4 + 2) * 9 + w];
                unsigned a3 = As[(ty4 + 3) * 9 + w];
                unsigned b0 = Bs[(tx4 + 0) * 9 + w];
                unsigned b1 = Bs[(tx4 + 1) * 9 + w];
                unsigned b2 = Bs[(tx4 + 2) * 9 + w];
                unsigned b3 = Bs[(tx4 + 3) * 9 + w];
                acc[0][0] |= a0 & b0; acc[0][1] |= a0 & b1; acc[0][2] |= a0 & b2; acc[0][3] |= a0 & b3;
                acc[1][0] |= a1 & b0; acc[1][1] |= a1 & b1; acc[1][2] |= a1 & b2; acc[1][3] |= a1 & b3;
                acc[2][0] |= a2 & b0; acc[2][1] |= a2 & b1; acc[2][2] |= a2 & b2; acc[2][3] |= a2 & b3;
                acc[3][0] |= a3 & b0; acc[3][1] |= a3 & b1; acc[3][2] |= a3 & b2; acc[3][3] |= a3 & b3;
            }
            bool d = true;
#pragma unroll
            for (int i = 0; i < 4; ++i)
#pragma unroll
                for (int j = 0; j < 4; ++j) d = d && (acc[i][j] != 0u);
            done = d;
        }
        if (__syncthreads_and(done ? 1 : 0)) break;
    }

    int word_half = tx >> 3;            // which of the 2 output words in this tile
    int shift = tx4 & 31;
#pragma unroll
    for (int i = 0; i < 4; ++i) {
        int r = rbase + ty4 + i;
        if (r < kk) {
            unsigned nib = 0;
            int cnt = 0;
#pragma unroll
            for (int j = 0; j < 4; ++j) {
                int c = cbase + tx4 + j;
                if (c < kk && acc[i][j]) { nib |= (1u << j); cnt++; }
            }
            if (nib) atomicOr(&obits[(ty4 + i) * 2 + word_half], nib << shift);
            if (cnt) atomicAdd(&rc[ty4 + i], (float)cnt);
        }
    }
    __syncthreads();
    if (tid < 128) {
        int rr = tid >> 1;
        int r = rbase + rr;
        int w = blockIdx.x * 2 + (tid & 1);
        if (r < kk && w < Wout) CB[(size_t)r * Wout + w] = obits[tid];
    }
    if (tid < 64) {
        int r = rbase + tid;
        if (r < kk && rc[tid] != 0.f) atomicAdd(&rowsum[r], rc[tid]);
    }
}

__global__ void k_zero(float* __restrict__ p, int n) {
    int i = blockIdx.x * 256 + threadIdx.x;
    if (i < n) p[i] = 0.f;
}

__global__ void k_scatter(const float* __restrict__ hsrc, const int* __restrict__ idx,
                          float* __restrict__ u) {
    int b = blockIdx.x, t = threadIdx.x;
    u[(size_t)idx[b] * DIMS + t] = hsrc[(size_t)b * DIMS + t];
}

__global__ void k_add(const float* __restrict__ a, const float* __restrict__ b,
                      float* __restrict__ o, int n) {
    int i = blockIdx.x * 256 + threadIdx.x;
    if (i < n) o[i] = a[i] + b[i];
}

extern "C" void kernel_launch(void* const* d_in, const int* in_sizes, int n_in,
                              void* d_out, int out_size) {
    (void)in_sizes; (void)n_in; (void)out_size;
    const float* g0   = (const float*)d_in[0];
    const float* h_in = (const float*)d_in[1];
    const float* dW   = (const float*)d_in[2];
    const float* db   = (const float*)d_in[3];
    const float* uW   = (const float*)d_in[4];
    const float* ub   = (const float*)d_in[5];
    const float* pW   = (const float*)d_in[6];
    const float* pb   = (const float*)d_in[7];
    const float* bW   = (const float*)d_in[8];
    const float* bb   = (const float*)d_in[9];
    float* out = (float*)d_out;
    float* out0 = out;                               // [N2,64]
    float* out1 = out + (size_t)N2 * DIMS;           // [N1,64]
    float* out2 = out1 + (size_t)N1 * DIMS;          // [N0,64]
    float* out3 = out2 + (size_t)N0 * DIMS;          // [N0,64]

    void* basep = nullptr;
    cudaGetSymbolAddress(&basep, g_arena);
    char* base = (char*)basep;
    unsigned* CB1  = (unsigned*)(base + A_CB1);
    unsigned* CB2  = (unsigned*)(base + A_CB2);
    unsigned* CB3  = (unsigned*)(base + A_CB3);
    unsigned* BITS = (unsigned*)(base + A_BITS);
    float*    T    = (float*)(base + A_T);
    float*    U    = (float*)(base + A_U);
    float*    Hb   = (float*)(base + A_H);
    float*    D0b  = (float*)(base + A_D0);
    float*    D1b  = (float*)(base + A_D1);
    float*    D2b  = (float*)(base + A_D2);
    float*    SC   = (float*)(base + A_SC);
    float*    SV   = (float*)(base + A_SV);
    int*      I0   = (int*)(base + A_I0);
    int*      I1   = (int*)(base + A_I1);
    int*      I2   = (int*)(base + A_I2);
    float*    RS1  = (float*)(base + A_RS1);
    float*    RS2  = (float*)(base + A_RS2);
    float*    RS3  = (float*)(base + A_RS3);

    // ---------------- down level 0 ----------------
    k_spmm_f<<<(N0 + 7) / 8, 256>>>(g0, h_in, T, N0);
    k_proj<<<(N0 + 3) / 4, 256>>>(T, dW, db, nullptr, D0b, N0);
    k_scores<<<(N0 + 7) / 8, 256>>>(D0b, pW, pb, SC, N0);
    k_sort<<<1, 1024>>>(SC, N0, N1, I0, SV);
    k_gather<<<N1, 64>>>(D0b, I0, SV, Hb);
    k_pack<<<(N1 * W0 + 7) / 8, 256>>>(g0, I0, BITS, N0, N1, W0);
    k_zero<<<(N1 + 255) / 256, 256>>>(RS1, N1);
    {
        dim3 grid((N1 + 63) / 64, (N1 + 63) / 64);
        k_pairb<<<grid, 256>>>(BITS, N1, W0, W1, CB1, RS1);
    }

    // ---------------- down level 1 ----------------
    k_spmm_bits<<<(N1 + 7) / 8, 256>>>(CB1, RS1, Hb, T, N1, W1);
    k_proj<<<(N1 + 3) / 4, 256>>>(T, dW + 4096, db + 64, nullptr, D1b, N1);
    k_scores<<<(N1 + 7) / 8, 256>>>(D1b, pW + 64, pb + 1, SC, N1);
    k_sort<<<1, 1024>>>(SC, N1, N2, I1, SV);
    k_gather<<<N2, 64>>>(D1b, I1, SV, Hb);
    k_packb<<<(N2 * W1 + 255) / 256, 256>>>(CB1, I1, BITS, N2, W1);
    k_zero<<<(N2 + 255) / 256, 256>>>(RS2, N2);
    {
        dim3 grid((N2 + 63) / 64, (N2 + 63) / 64);
        k_pairb<<<grid, 256>>>(BITS, N2, W1, W2, CB2, RS2);
    }

    // ---------------- down level 2 ----------------
    k_gemm_bits<<<(N2 + 15) / 16, 256>>>(CB2, RS2, Hb, T, N2, W2);
    k_proj<<<(N2 + 3) / 4, 256>>>(T, dW + 8192, db + 128, nullptr, D2b, N2);
    k_scores<<<(N2 + 7) / 8, 256>>>(D2b, pW + 128, pb + 2, SC, N2);
    k_sort<<<1, 1024>>>(SC, N2, N3, I2, SV);
    k_gather<<<N3, 64>>>(D2b, I2, SV, Hb);
    k_packb<<<(N3 * W2 + 255) / 256, 256>>>(CB2, I2, BITS, N3, W2);
    k_zero<<<(N3 + 255) / 256, 256>>>(RS3, N3);
    {
        dim3 grid((N3 + 63) / 64, (N3 + 63) / 64);
        k_pairb<<<grid, 256>>>(BITS, N3, W2, W3, CB3, RS3);
    }

    // ---------------- bottom ----------------
    k_gemm_bits<<<(N3 + 15) / 16, 256>>>(CB3, RS3, Hb, T, N3, W3);
    k_proj<<<(N3 + 3) / 4, 256>>>(T, bW, bb, nullptr, Hb, N3);

    // ---------------- up level 0 (uses CB2, I2) ----------------
    k_zero<<<(N2 * DIMS + 255) / 256, 256>>>(U, N2 * DIMS);
    k_scatter<<<N3, 64>>>(Hb, I2, U);
    k_gemm_bits<<<(N2 + 15) / 16, 256>>>(CB2, RS2, U, T, N2, W2);
    k_proj<<<(N2 + 3) / 4, 256>>>(T, uW, ub, D2b, out0, N2);

    // ---------------- up level 1 (uses CB1, I1) ----------------
    k_zero<<<(N1 * DIMS + 255) / 256, 256>>>(U, N1 * DIMS);
    k_scatter<<<N2, 64>>>(out0, I1, U);
    k_spmm_bits<<<(N1 + 7) / 8, 256>>>(CB1, RS1, U, T, N1, W1);
    k_proj<<<(N1 + 3) / 4, 256>>>(T, uW + 4096, ub + 64, D1b, out1, N1);

    // ---------------- up level 2 (uses g0, I0) ----------------
    k_zero<<<(N0 * DIMS + 255) / 256, 256>>>(U, N0 * DIMS);
    k_scatter<<<N1, 64>>>(out1, I0, U);
    k_spmm_f<<<(N0 + 7) / 8, 256>>>(g0, U, T, N0);
    k_proj<<<(N0 + 3) / 4, 256>>>(T, uW + 8192, ub + 128, D0b, out2, N0);

    // ---------------- final residual ----------------
    k_add<<<(N0 * DIMS + 255) / 256, 256>>>(out2, h_in, out3, N0 * DIMS);
}

// round 8
// speedup vs baseline: 2.0611x; 1.2684x over previous
#include <cuda_runtime.h>
#include <cstdint>
#include <cstddef>

#define N0 4096
#define N1 3686
#define N2 2580
#define N3 1548
#define DIMS 64
#define W0 128   /* ceil(N0/32) */
#define W1 116   /* ceil(N1/32) */
#define W2 81    /* ceil(N2/32) */
#define W3 49    /* ceil(N3/32) */
#define SORTN 4096
#define FULLMASK 0xffffffffu

static __host__ __device__ constexpr size_t alignup(size_t x) { return (x + 255) & ~(size_t)255; }

static constexpr size_t A_CB0  = 0;
static constexpr size_t A_CB1  = A_CB0  + alignup((size_t)N0 * W0 * 4);
static constexpr size_t A_CB2  = A_CB1  + alignup((size_t)N1 * W1 * 4);
static constexpr size_t A_CB3  = A_CB2  + alignup((size_t)N2 * W2 * 4);
static constexpr size_t A_BITS = A_CB3  + alignup((size_t)N3 * W3 * 4);
static constexpr size_t A_T    = A_BITS + alignup((size_t)N2 * W1 * 4);
static constexpr size_t A_U    = A_T    + alignup((size_t)N0 * DIMS * 4);
static constexpr size_t A_H    = A_U    + alignup((size_t)N0 * DIMS * 4);
static constexpr size_t A_D0   = A_H    + alignup((size_t)N0 * DIMS * 4);
static constexpr size_t A_D1   = A_D0   + alignup((size_t)N0 * DIMS * 4);
static constexpr size_t A_D2   = A_D1   + alignup((size_t)N1 * DIMS * 4);
static constexpr size_t A_SC   = A_D2   + alignup((size_t)N2 * DIMS * 4);
static constexpr size_t A_SV   = A_SC   + alignup((size_t)SORTN * 4);
static constexpr size_t A_I0   = A_SV   + alignup((size_t)SORTN * 4);
static constexpr size_t A_I1   = A_I0   + alignup((size_t)SORTN * 4);
static constexpr size_t A_I2   = A_I1   + alignup((size_t)SORTN * 4);
static constexpr size_t A_RS0  = A_I2   + alignup((size_t)SORTN * 4);
static constexpr size_t A_RS1  = A_RS0  + alignup((size_t)SORTN * 4);
static constexpr size_t A_RS2  = A_RS1  + alignup((size_t)SORTN * 4);
static constexpr size_t A_RS3  = A_RS2  + alignup((size_t)SORTN * 4);
static constexpr size_t ARENA_BYTES = A_RS3 + alignup((size_t)SORTN * 4);

__device__ __align__(256) unsigned char g_arena[ARENA_BYTES];

// ---- XLA f32 tanh (Eigen ptanh) + logistic expansion ----
__device__ __forceinline__ float xla_tanhf(float x) {
    if (fabsf(x) < 0.0004f) return x;
    float xc = fminf(fmaxf(x, -7.90531110763549805f), 7.90531110763549805f);
    float x2 = xc * xc;
    float p = -2.76076847742355e-16f;
    p = fmaf(p, x2, 2.00018790482477e-13f);
    p = fmaf(p, x2, -8.60467152213735e-11f);
    p = fmaf(p, x2, 5.12229709037114e-08f);
    p = fmaf(p, x2, 1.48572235717979e-05f);
    p = fmaf(p, x2, 6.37261928875436e-04f);
    p = fmaf(p, x2, 4.89352455891786e-03f);
    float num = xc * p;
    float q = 1.19825839466702e-06f;
    q = fmaf(q, x2, 1.18534705686654e-04f);
    q = fmaf(q, x2, 2.26843463243900e-03f);
    q = fmaf(q, x2, 4.89352518554385e-03f);
    return num / q;
}
__device__ __forceinline__ float xla_sigmoidf(float x) {
    return fmaf(0.5f, xla_tanhf(0.5f * x), 0.5f);
}

// ---- bit-pack (g != 0) full rows (level-0 input) ----
__global__ void k_pack(const float* __restrict__ g, unsigned* __restrict__ bits,
                       int n, int Wl) {
    int gw = (int)((blockIdx.x * (unsigned)blockDim.x + threadIdx.x) >> 5);
    int lane = threadIdx.x & 31;
    if (gw >= n * Wl) return;
    int r = gw / Wl, w = gw - r * Wl;
    int c = w * 32 + lane;
    float v = (c < n) ? g[(size_t)r * n + c] : 0.f;
    unsigned m = __ballot_sync(FULLMASK, v != 0.f);
    if (lane == 0) bits[(size_t)r * Wl + w] = m;
}

// ---- RS[r] = (float) popcount(row r) ----
__global__ void k_count(const unsigned* __restrict__ CB, float* __restrict__ RS,
                        int n, int Wl) {
    int warp = (int)((blockIdx.x * (unsigned)blockDim.x + threadIdx.x) >> 5);
    int lane = threadIdx.x & 31;
    if (warp >= n) return;
    const unsigned* row = CB + (size_t)warp * Wl;
    int c = 0;
    for (int w = lane; w < Wl; w += 32) c += __popc(row[w]);
#pragma unroll
    for (int off = 16; off > 0; off >>= 1) c += __shfl_xor_sync(FULLMASK, c, off);
    if (lane == 0) RS[warp] = (float)c;
}

// ---- t = G @ h where G = bits * (1/RS[row]); warp per row, ffs ascending ----
__global__ void k_spmm_bits(const unsigned* __restrict__ CB, const float* __restrict__ RS,
                            const float* __restrict__ h, float* __restrict__ t,
                            int n, int Wl) {
    int warp = (int)((blockIdx.x * (unsigned)blockDim.x + threadIdx.x) >> 5);
    int lane = threadIdx.x & 31;
    if (warp >= n) return;
    const unsigned* row = CB + (size_t)warp * Wl;
    float inv = 1.0f / RS[warp];
    float a0 = 0.f, a1 = 0.f;
    for (int wb = 0; wb < Wl; wb += 32) {
        unsigned myw = (wb + lane < Wl) ? row[wb + lane] : 0u;
        unsigned any = __ballot_sync(FULLMASK, myw != 0u);
        while (any) {
            int s = __ffs(any) - 1;
            any &= any - 1;
            unsigned word = __shfl_sync(FULLMASK, myw, s);
            int cb = (wb + s) << 5;
            while (word) {
                int c = cb + __ffs(word) - 1;
                word &= word - 1;
                const float* hp = h + (size_t)c * DIMS;
                a0 = fmaf(inv, hp[lane], a0);
                a1 = fmaf(inv, hp[lane + 32], a1);
            }
        }
    }
    t[(size_t)warp * DIMS + lane]      = a0;
    t[(size_t)warp * DIMS + lane + 32] = a1;
}

// ---- t = G @ h, smem-tiled dense sweep (G from bits), 16-row tiles ----
__global__ void k_gemm_bits(const unsigned* __restrict__ CB, const float* __restrict__ RS,
                            const float* __restrict__ h, float* __restrict__ t,
                            int n, int Wl) {
    __shared__ float gs[16][65];
    __shared__ float hs[64][64];
    __shared__ float invs[16];
    int tid = threadIdx.x;
    int tx = tid & 15, ty = tid >> 4;
    int tx4 = tx * 4;
    int rbase = blockIdx.x * 16;
    if (tid < 16) {
        int r = rbase + tid;
        invs[tid] = (r < n) ? 1.0f / RS[r] : 0.f;
    }
    __syncthreads();
    float acc[4] = {0.f, 0.f, 0.f, 0.f};

    for (int kb = 0; kb < n; kb += 64) {
        for (int i2 = tid; i2 < 1024; i2 += 256) {
            int rr = i2 >> 6, cc = i2 & 63;
            int gr = rbase + rr, gc = kb + cc;
            bool bit = (gr < n && gc < n) &&
                       ((CB[(size_t)gr * Wl + (gc >> 5)] >> (gc & 31)) & 1u);
            gs[rr][cc] = bit ? invs[rr] : 0.f;
        }
        for (int i2 = tid; i2 < 4096; i2 += 256) {
            int rr = i2 >> 6, cc = i2 & 63;
            int hr = kb + rr;
            hs[rr][cc] = (hr < n) ? h[(size_t)hr * DIMS + cc] : 0.f;
        }
        __syncthreads();
#pragma unroll 8
        for (int kk = 0; kk < 64; ++kk) {
            float a = gs[ty][kk];
            acc[0] = fmaf(a, hs[kk][tx4 + 0], acc[0]);
            acc[1] = fmaf(a, hs[kk][tx4 + 1], acc[1]);
            acc[2] = fmaf(a, hs[kk][tx4 + 2], acc[2]);
            acc[3] = fmaf(a, hs[kk][tx4 + 3], acc[3]);
        }
        __syncthreads();
    }
    int r = rbase + ty;
    if (r < n) {
#pragma unroll
        for (int j = 0; j < 4; ++j)
            t[(size_t)r * DIMS + tx4 + j] = acc[j];
    }
}

// ---- out = relu((t @ W) + b) [+ res] ----
__global__ void k_proj(const float* __restrict__ t, const float* __restrict__ Wm,
                       const float* __restrict__ b, const float* __restrict__ res,
                       float* __restrict__ out, int n) {
    __shared__ float Ws[64 * 64];
    __shared__ float Ts[4 * 64];
    int tid = threadIdx.x;
    int d = tid & 63;
    int r4 = tid >> 6;
    int row = blockIdx.x * 4 + r4;
    for (int i = tid; i < 4096; i += 256) Ws[i] = Wm[i];
    {
        int rr = blockIdx.x * 4 + (tid >> 6);
        Ts[tid] = (rr < n) ? t[(size_t)rr * DIMS + (tid & 63)] : 0.f;
    }
    __syncthreads();
    if (row < n) {
        float acc = 0.f;
#pragma unroll
        for (int k = 0; k < 64; ++k)
            acc = fmaf(Ts[r4 * 64 + k], Ws[k * 64 + d], acc);
        acc = acc + b[d];
        acc = fmaxf(acc, 0.f);
        if (res) acc += res[(size_t)row * DIMS + d];
        out[(size_t)row * DIMS + d] = acc;
    }
}

// ---- final proj: out2 = relu(tW+b)+res ; out3 = out2 + h_in ----
__global__ void k_proj_final(const float* __restrict__ t, const float* __restrict__ Wm,
                             const float* __restrict__ b, const float* __restrict__ res,
                             const float* __restrict__ hin,
                             float* __restrict__ out2, float* __restrict__ out3, int n) {
    __shared__ float Ws[64 * 64];
    __shared__ float Ts[4 * 64];
    int tid = threadIdx.x;
    int d = tid & 63;
    int r4 = tid >> 6;
    int row = blockIdx.x * 4 + r4;
    for (int i = tid; i < 4096; i += 256) Ws[i] = Wm[i];
    {
        int rr = blockIdx.x * 4 + (tid >> 6);
        Ts[tid] = (rr < n) ? t[(size_t)rr * DIMS + (tid & 63)] : 0.f;
    }
    __syncthreads();
    if (row < n) {
        float acc = 0.f;
#pragma unroll
        for (int k = 0; k < 64; ++k)
            acc = fmaf(Ts[r4 * 64 + k], Ws[k * 64 + d], acc);
        acc = acc + b[d];
        acc = fmaxf(acc, 0.f);
        acc += res[(size_t)row * DIMS + d];
        out2[(size_t)row * DIMS + d] = acc;
        out3[(size_t)row * DIMS + d] = acc + hin[(size_t)row * DIMS + d];
    }
}

// ---- scores = xla_sigmoid(h @ pw + pb) ----
__global__ void k_scores(const float* __restrict__ h, const float* __restrict__ pw,
                         const float* __restrict__ pb, float* __restrict__ sc, int n) {
    int warp = (int)((blockIdx.x * (unsigned)blockDim.x + threadIdx.x) >> 5);
    int lane = threadIdx.x & 31;
    if (warp >= n) return;
    float acc = h[(size_t)warp * DIMS + lane] * pw[lane];
    acc = fmaf(h[(size_t)warp * DIMS + lane + 32], pw[lane + 32], acc);
#pragma unroll
    for (int off = 16; off > 0; off >>= 1) acc += __shfl_xor_sync(FULLMASK, acc, off);
    if (lane == 0) sc[warp] = xla_sigmoidf(acc + pb[0]);
}

// ---- exact bitonic top-k: (score desc, idx asc) via packed u64 keys ----
__global__ void k_sort(const float* __restrict__ sc, int n, int k,
                       int* __restrict__ idx_out, float* __restrict__ vals_out) {
    __shared__ unsigned long long ks[SORTN];
    int tid = threadIdx.x;
    for (int j = tid; j < SORTN; j += 1024) {
        if (j < n) {
            unsigned fb = __float_as_uint(sc[j]);
            ks[j] = ((unsigned long long)(~fb) << 32) | (unsigned)j;
        } else {
            ks[j] = 0xFFFFFFFFFFFFFFFFull;
        }
    }
    __syncthreads();
    for (int size = 2; size <= SORTN; size <<= 1) {
        for (int stride = size >> 1; stride > 0; stride >>= 1) {
            for (int t2 = tid; t2 < SORTN / 2; t2 += 1024) {
                int i = 2 * t2 - (t2 & (stride - 1));
                int j = i + stride;
                unsigned long long ki = ks[i], kj = ks[j];
                bool asc = ((i & size) == 0);
                bool sw = asc ? (ki > kj) : (ki < kj);
                if (sw) { ks[i] = kj; ks[j] = ki; }
            }
            __syncthreads();
        }
    }
    for (int j = tid; j < k; j += 1024) {
        unsigned long long key = ks[j];
        idx_out[j] = (int)(key & 0xFFFFFFFFull);
        vals_out[j] = __uint_as_float(~(unsigned)(key >> 32));
    }
}

__global__ void k_gather(const float* __restrict__ hsrc, const int* __restrict__ idx,
                         const float* __restrict__ vals, float* __restrict__ hout) {
    int b = blockIdx.x, t = threadIdx.x;
    hout[(size_t)b * DIMS + t] = hsrc[(size_t)idx[b] * DIMS + t] * vals[b];
}

// ---- level-0 2-hop via row-OR over sparse neighbors; packed gathered output ----
__global__ void k_rowor(const unsigned* __restrict__ BITS0, const int* __restrict__ idx,
                        unsigned* __restrict__ CB1o, float* __restrict__ RS1o) {
    __shared__ unsigned own[W0];
    __shared__ unsigned accs[W0];
    __shared__ int cnt_sh;
    int i = blockIdx.x;
    int t = threadIdx.x;            // 128 threads
    own[t] = BITS0[(size_t)idx[i] * W0 + t];
    if (t == 0) cnt_sh = 0;
    __syncthreads();
    unsigned a = 0;
    for (int w2 = 0; w2 < W0; ++w2) {
        unsigned word = own[w2];
        while (word) {
            int c = (w2 << 5) + __ffs(word) - 1;
            word &= word - 1;
            a |= BITS0[(size_t)c * W0 + t];
        }
    }
    accs[t] = a;
    __syncthreads();
    int lane = t & 31, wp = t >> 5;  // 4 warps
    int cnt = 0;
    for (int ow = wp; ow < W1; ow += 4) {
        int j = (ow << 5) + lane;
        unsigned bit = 0;
        if (j < N1) {
            int col = idx[j];
            bit = (accs[col >> 5] >> (col & 31)) & 1u;
        }
        unsigned m = __ballot_sync(FULLMASK, bit);
        if (lane == 0) {
            CB1o[(size_t)i * W1 + ow] = m;
            cnt += __popc(m);
        }
    }
    if (lane == 0 && cnt) atomicAdd(&cnt_sh, cnt);
    __syncthreads();
    if (t == 0) RS1o[i] = (float)cnt_sh;
}

// ---- gather packed bit rows by idx ----
__global__ void k_packb(const unsigned* __restrict__ src, const int* __restrict__ idx,
                        unsigned* __restrict__ dst, int rows, int Wl) {
    int i = blockIdx.x * 256 + threadIdx.x;
    if (i >= rows * Wl) return;
    int r = i / Wl, w = i - r * Wl;
    dst[(size_t)r * Wl + w] = src[(size_t)idx[r] * Wl + w];
}

// ---- pairwise 2-hop with PACKED output: CB bits + rowsum ----
__global__ void k_pairb(const unsigned* __restrict__ A, int kk, int Wl, int Wout,
                        unsigned* __restrict__ CB, float* __restrict__ rowsum) {
    __shared__ unsigned As[64 * 9];
    __shared__ unsigned Bs[64 * 9];
    __shared__ unsigned obits[128];
    __shared__ float rc[64];
    int tid = threadIdx.x;
    int tx = tid & 15, ty = tid >> 4;
    int rbase = blockIdx.y * 64, cbase = blockIdx.x * 64;
    int ty4 = ty * 4, tx4 = tx * 4;
    if (tid < 64) rc[tid] = 0.f;
    if (tid < 128) obits[tid] = 0u;

    unsigned acc[4][4];
#pragma unroll
    for (int i = 0; i < 4; ++i)
#pragma unroll
        for (int j = 0; j < 4; ++j) {
            bool valid = (rbase + ty4 + i < kk) && (cbase + tx4 + j < kk);
            acc[i][j] = valid ? 0u : 1u;
        }

    bool done = false;
    for (int ch = 0; ch < Wl; ch += 8) {
        for (int i2 = tid; i2 < 512; i2 += 256) {
            int rr = i2 >> 3, ww = i2 & 7;
            int gw = ch + ww;
            int grow = rbase + rr;
            int gcol = cbase + rr;
            As[rr * 9 + ww] = (grow < kk && gw < Wl) ? A[(size_t)grow * Wl + gw] : 0u;
            Bs[rr * 9 + ww] = (gcol < kk && gw < Wl) ? A[(size_t)gcol * Wl + gw] : 0u;
        }
        __syncthreads();
        if (!done) {
#pragma unroll
            for (int w = 0; w < 8; ++w) {
                unsigned a0 = As[(ty4 + 0) * 9 + w];
                unsigned a1 = As[(ty4 + 1) * 9 + w];
                unsigned a2 = As[(ty4 + 2) * 9 + w];
                unsigned a3 = As[(ty4 + 3) * 9 + w];
                unsigned b0 = Bs[(tx4 + 0) * 9 + w];
                unsigned b1 = Bs[(tx4 + 1) * 9 + w];
                unsigned b2 = Bs[(tx4 + 2) * 9 + w];
                unsigned b3 = Bs[(tx4 + 3) * 9 + w];
                acc[0][0] |= a0 & b0; acc[0][1] |= a0 & b1; acc[0][2] |= a0 & b2; acc[0][3] |= a0 & b3;
                acc[1][0] |= a1 & b0; acc[1][1] |= a1 & b1; acc[1][2] |= a1 & b2; acc[1][3] |= a1 & b3;
                acc[2][0] |= a2 & b0; acc[2][1] |= a2 & b1; acc[2][2] |= a2 & b2; acc[2][3] |= a2 & b3;
                acc[3][0] |= a3 & b0; acc[3][1] |= a3 & b1; acc[3][2] |= a3 & b2; acc[3][3] |= a3 & b3;
            }
            bool d = true;
#pragma unroll
            for (int i = 0; i < 4; ++i)
#pragma unroll
                for (int j = 0; j < 4; ++j) d = d && (acc[i][j] != 0u);
            done = d;
        }
        if (__syncthreads_and(done ? 1 : 0)) break;
    }

    int word_half = tx >> 3;
    int shift = tx4 & 31;
#pragma unroll
    for (int i = 0; i < 4; ++i) {
        int r = rbase + ty4 + i;
        if (r < kk) {
            unsigned nib = 0;
            int cnt = 0;
#pragma unroll
            for (int j = 0; j < 4; ++j) {
                int c = cbase + tx4 + j;
                if (c < kk && acc[i][j]) { nib |= (1u << j); cnt++; }
            }
            if (nib) atomicOr(&obits[(ty4 + i) * 2 + word_half], nib << shift);
            if (cnt) atomicAdd(&rc[ty4 + i], (float)cnt);
        }
    }
    __syncthreads();
    if (tid < 128) {
        int rr = tid >> 1;
        int r = rbase + rr;
        int w = blockIdx.x * 2 + (tid & 1);
        if (r < kk && w < Wout) CB[(size_t)r * Wout + w] = obits[tid];
    }
    if (tid < 64) {
        int r = rbase + tid;
        if (r < kk && rc[tid] != 0.f) atomicAdd(&rowsum[r], rc[tid]);
    }
}

__global__ void k_zero(float* __restrict__ p, int n) {
    int i = blockIdx.x * 256 + threadIdx.x;
    if (i < n) p[i] = 0.f;
}

__global__ void k_scatter(const float* __restrict__ hsrc, const int* __restrict__ idx,
                          float* __restrict__ u) {
    int b = blockIdx.x, t = threadIdx.x;
    u[(size_t)idx[b] * DIMS + t] = hsrc[(size_t)b * DIMS + t];
}

extern "C" void kernel_launch(void* const* d_in, const int* in_sizes, int n_in,
                              void* d_out, int out_size) {
    (void)in_sizes; (void)n_in; (void)out_size;
    const float* g0   = (const float*)d_in[0];
    const float* h_in = (const float*)d_in[1];
    const float* dW   = (const float*)d_in[2];
    const float* db   = (const float*)d_in[3];
    const float* uW   = (const float*)d_in[4];
    const float* ub   = (const float*)d_in[5];
    const float* pW   = (const float*)d_in[6];
    const float* pb   = (const float*)d_in[7];
    const float* bW   = (const float*)d_in[8];
    const float* bb   = (const float*)d_in[9];
    float* out = (float*)d_out;
    float* out0 = out;                               // [N2,64]
    float* out1 = out + (size_t)N2 * DIMS;           // [N1,64]
    float* out2 = out1 + (size_t)N1 * DIMS;          // [N0,64]
    float* out3 = out2 + (size_t)N0 * DIMS;          // [N0,64]

    void* basep = nullptr;
    cudaGetSymbolAddress(&basep, g_arena);
    char* base = (char*)basep;
    unsigned* CB0  = (unsigned*)(base + A_CB0);
    unsigned* CB1  = (unsigned*)(base + A_CB1);
    unsigned* CB2  = (unsigned*)(base + A_CB2);
    unsigned* CB3  = (unsigned*)(base + A_CB3);
    unsigned* BITS = (unsigned*)(base + A_BITS);
    float*    T    = (float*)(base + A_T);
    float*    U    = (float*)(base + A_U);
    float*    Hb   = (float*)(base + A_H);
    float*    D0b  = (float*)(base + A_D0);
    float*    D1b  = (float*)(base + A_D1);
    float*    D2b  = (float*)(base + A_D2);
    float*    SC   = (float*)(base + A_SC);
    float*    SV   = (float*)(base + A_SV);
    int*      I0   = (int*)(base + A_I0);
    int*      I1   = (int*)(base + A_I1);
    int*      I2   = (int*)(base + A_I2);
    float*    RS0  = (float*)(base + A_RS0);
    float*    RS1  = (float*)(base + A_RS1);
    float*    RS2  = (float*)(base + A_RS2);
    float*    RS3  = (float*)(base + A_RS3);

    // ---------------- down level 0 ----------------
    k_pack<<<(N0 * W0 + 7) / 8, 256>>>(g0, CB0, N0, W0);
    k_count<<<(N0 + 7) / 8, 256>>>(CB0, RS0, N0, W0);
    k_spmm_bits<<<(N0 + 7) / 8, 256>>>(CB0, RS0, h_in, T, N0, W0);
    k_proj<<<(N0 + 3) / 4, 256>>>(T, dW, db, nullptr, D0b, N0);
    k_scores<<<(N0 + 7) / 8, 256>>>(D0b, pW, pb, SC, N0);
    k_sort<<<1, 1024>>>(SC, N0, N1, I0, SV);
    k_gather<<<N1, 64>>>(D0b, I0, SV, Hb);
    k_rowor<<<N1, 128>>>(CB0, I0, CB1, RS1);

    // ---------------- down level 1 ----------------
    k_spmm_bits<<<(N1 + 7) / 8, 256>>>(CB1, RS1, Hb, T, N1, W1);
    k_proj<<<(N1 + 3) / 4, 256>>>(T, dW + 4096, db + 64, nullptr, D1b, N1);
    k_scores<<<(N1 + 7) / 8, 256>>>(D1b, pW + 64, pb + 1, SC, N1);
    k_sort<<<1, 1024>>>(SC, N1, N2, I1, SV);
    k_gather<<<N2, 64>>>(D1b, I1, SV, Hb);
    k_packb<<<(N2 * W1 + 255) / 256, 256>>>(CB1, I1, BITS, N2, W1);
    k_zero<<<(N2 + 255) / 256, 256>>>(RS2, N2);
    {
        dim3 grid((N2 + 63) / 64, (N2 + 63) / 64);
        k_pairb<<<grid, 256>>>(BITS, N2, W1, W2, CB2, RS2);
    }

    // ---------------- down level 2 ----------------
    k_gemm_bits<<<(N2 + 15) / 16, 256>>>(CB2, RS2, Hb, T, N2, W2);
    k_proj<<<(N2 + 3) / 4, 256>>>(T, dW + 8192, db + 128, nullptr, D2b, N2);
    k_scores<<<(N2 + 7) / 8, 256>>>(D2b, pW + 128, pb + 2, SC, N2);
    k_sort<<<1, 1024>>>(SC, N2, N3, I2, SV);
    k_gather<<<N3, 64>>>(D2b, I2, SV, Hb);
    k_packb<<<(N3 * W2 + 255) / 256, 256>>>(CB2, I2, BITS, N3, W2);
    k_zero<<<(N3 + 255) / 256, 256>>>(RS3, N3);
    {
        dim3 grid((N3 + 63) / 64, (N3 + 63) / 64);
        k_pairb<<<grid, 256>>>(BITS, N3, W2, W3, CB3, RS3);
    }

    // ---------------- bottom ----------------
    k_gemm_bits<<<(N3 + 15) / 16, 256>>>(CB3, RS3, Hb, T, N3, W3);
    k_proj<<<(N3 + 3) / 4, 256>>>(T, bW, bb, nullptr, Hb, N3);

    // ---------------- up level 0 (uses CB2, I2) ----------------
    k_zero<<<(N2 * DIMS + 255) / 256, 256>>>(U, N2 * DIMS);
    k_scatter<<<N3, 64>>>(Hb, I2, U);
    k_gemm_bits<<<(N2 + 15) / 16, 256>>>(CB2, RS2, U, T, N2, W2);
    k_proj<<<(N2 + 3) / 4, 256>>>(T, uW, ub, D2b, out0, N2);

    // ---------------- up level 1 (uses CB1, I1) ----------------
    k_zero<<<(N1 * DIMS + 255) / 256, 256>>>(U, N1 * DIMS);
    k_scatter<<<N2, 64>>>(out0, I1, U);
    k_spmm_bits<<<(N1 + 7) / 8, 256>>>(CB1, RS1, U, T, N1, W1);
    k_proj<<<(N1 + 3) / 4, 256>>>(T, uW + 4096, ub + 64, D1b, out1, N1);

    // ---------------- up level 2 (uses CB0, I0) ----------------
    k_zero<<<(N0 * DIMS + 255) / 256, 256>>>(U, N0 * DIMS);
    k_scatter<<<N1, 64>>>(out1, I0, U);
    k_spmm_bits<<<(N0 + 7) / 8, 256>>>(CB0, RS0, U, T, N0, W0);
    k_proj_final<<<(N0 + 3) / 4, 256>>>(T, uW + 8192, ub + 128, D0b, h_in, out2, out3, N0);
}

// round 9
// speedup vs baseline: 2.3017x; 1.1167x over previous
#include <cuda_runtime.h>
#include <cstdint>
#include <cstddef>

#define N0 4096
#define N1 3686
#define N2 2580
#define N3 1548
#define DIMS 64
#define W0 128   /* ceil(N0/32) */
#define W1 116   /* ceil(N1/32) */
#define W2 81    /* ceil(N2/32) */
#define W3 49    /* ceil(N3/32) */
#define SORTN 4096
#define FULLMASK 0xffffffffu

static __host__ __device__ constexpr size_t alignup(size_t x) { return (x + 255) & ~(size_t)255; }

static constexpr size_t A_CB0  = 0;
static constexpr size_t A_CB1  = A_CB0  + alignup((size_t)N0 * W0 * 4);
static constexpr size_t A_CB2  = A_CB1  + alignup((size_t)N1 * W1 * 4);
static constexpr size_t A_CB3  = A_CB2  + alignup((size_t)N2 * W2 * 4);
static constexpr size_t A_BITS = A_CB3  + alignup((size_t)N3 * W3 * 4);
static constexpr size_t A_T    = A_BITS + alignup((size_t)N2 * W1 * 4);
static constexpr size_t A_U    = A_T    + alignup((size_t)N0 * DIMS * 4);
static constexpr size_t A_H    = A_U    + alignup((size_t)N0 * DIMS * 4);
static constexpr size_t A_D0   = A_H    + alignup((size_t)N0 * DIMS * 4);
static constexpr size_t A_D1   = A_D0   + alignup((size_t)N0 * DIMS * 4);
static constexpr size_t A_D2   = A_D1   + alignup((size_t)N1 * DIMS * 4);
static constexpr size_t A_KEYS = A_D2   + alignup((size_t)N2 * DIMS * 4);
static constexpr size_t A_SV   = A_KEYS + alignup((size_t)SORTN * 8);
static constexpr size_t A_I0   = A_SV   + alignup((size_t)SORTN * 4);
static constexpr size_t A_I1   = A_I0   + alignup((size_t)SORTN * 4);
static constexpr size_t A_I2   = A_I1   + alignup((size_t)SORTN * 4);
static constexpr size_t A_RS0  = A_I2   + alignup((size_t)SORTN * 4);
static constexpr size_t A_RS1  = A_RS0  + alignup((size_t)SORTN * 4);
static constexpr size_t A_RS2  = A_RS1  + alignup((size_t)SORTN * 4);
static constexpr size_t A_RS3  = A_RS2  + alignup((size_t)SORTN * 4);
static constexpr size_t ARENA_BYTES = A_RS3 + alignup((size_t)SORTN * 4);

__device__ __align__(256) unsigned char g_arena[ARENA_BYTES];

// ---- XLA f32 tanh (Eigen ptanh) + logistic expansion ----
__device__ __forceinline__ float xla_tanhf(float x) {
    if (fabsf(x) < 0.0004f) return x;
    float xc = fminf(fmaxf(x, -7.90531110763549805f), 7.90531110763549805f);
    float x2 = xc * xc;
    float p = -2.76076847742355e-16f;
    p = fmaf(p, x2, 2.00018790482477e-13f);
    p = fmaf(p, x2, -8.60467152213735e-11f);
    p = fmaf(p, x2, 5.12229709037114e-08f);
    p = fmaf(p, x2, 1.48572235717979e-05f);
    p = fmaf(p, x2, 6.37261928875436e-04f);
    p = fmaf(p, x2, 4.89352455891786e-03f);
    float num = xc * p;
    float q = 1.19825839466702e-06f;
    q = fmaf(q, x2, 1.18534705686654e-04f);
    q = fmaf(q, x2, 2.26843463243900e-03f);
    q = fmaf(q, x2, 4.89352518554385e-03f);
    return num / q;
}
__device__ __forceinline__ float xla_sigmoidf(float x) {
    return fmaf(0.5f, xla_tanhf(0.5f * x), 0.5f);
}

// ---- fused: bit-pack (g != 0) + popcount rowsum; block per row ----
__global__ void k_packcnt(const float* __restrict__ g, unsigned* __restrict__ bits,
                          float* __restrict__ RS, int n, int Wl) {
    __shared__ int wcnt[8];
    int r = blockIdx.x;
    int tid = threadIdx.x;
    int lane = tid & 31, wp = tid >> 5;      // 8 warps
    const float* row = g + (size_t)r * n;
    int cnt = 0;
    for (int w = wp; w < Wl; w += 8) {
        int c = (w << 5) + lane;
        float v = (c < n) ? row[c] : 0.f;
        unsigned m = __ballot_sync(FULLMASK, v != 0.f);
        if (lane == 0) { bits[(size_t)r * Wl + w] = m; cnt += __popc(m); }
    }
    if (lane == 0) wcnt[wp] = cnt;
    __syncthreads();
    if (tid == 0) {
        int s = 0;
#pragma unroll
        for (int i = 0; i < 8; ++i) s += wcnt[i];
        RS[r] = (float)s;
    }
}

// ---- RS[r] = (float) popcount(row r) ----
__global__ void k_count(const unsigned* __restrict__ CB, float* __restrict__ RS,
                        int n, int Wl) {
    int warp = (int)((blockIdx.x * (unsigned)blockDim.x + threadIdx.x) >> 5);
    int lane = threadIdx.x & 31;
    if (warp >= n) return;
    const unsigned* row = CB + (size_t)warp * Wl;
    int c = 0;
    for (int w = lane; w < Wl; w += 32) c += __popc(row[w]);
#pragma unroll
    for (int off = 16; off > 0; off >>= 1) c += __shfl_xor_sync(FULLMASK, c, off);
    if (lane == 0) RS[warp] = (float)c;
}

// ---- t = G @ h where G = bits * (1/RS[row]); warp per row, ffs ascending ----
__global__ void k_spmm_bits(const unsigned* __restrict__ CB, const float* __restrict__ RS,
                            const float* __restrict__ h, float* __restrict__ t,
                            int n, int Wl) {
    int warp = (int)((blockIdx.x * (unsigned)blockDim.x + threadIdx.x) >> 5);
    int lane = threadIdx.x & 31;
    if (warp >= n) return;
    const unsigned* row = CB + (size_t)warp * Wl;
    float inv = 1.0f / RS[warp];
    float a0 = 0.f, a1 = 0.f;
    for (int wb = 0; wb < Wl; wb += 32) {
        unsigned myw = (wb + lane < Wl) ? row[wb + lane] : 0u;
        unsigned any = __ballot_sync(FULLMASK, myw != 0u);
        while (any) {
            int s = __ffs(any) - 1;
            any &= any - 1;
            unsigned word = __shfl_sync(FULLMASK, myw, s);
            int cb = (wb + s) << 5;
            while (word) {
                int c = cb + __ffs(word) - 1;
                word &= word - 1;
                const float* hp = h + (size_t)c * DIMS;
                a0 = fmaf(inv, hp[lane], a0);
                a1 = fmaf(inv, hp[lane + 32], a1);
            }
        }
    }
    t[(size_t)warp * DIMS + lane]      = a0;
    t[(size_t)warp * DIMS + lane + 32] = a1;
}

// ---- t = G @ h, smem-tiled dense sweep (G from bits), 16-row tiles ----
__global__ void k_gemm_bits(const unsigned* __restrict__ CB, const float* __restrict__ RS,
                            const float* __restrict__ h, float* __restrict__ t,
                            int n, int Wl) {
    __shared__ float gs[16][65];
    __shared__ float hs[64][64];
    __shared__ float invs[16];
    int tid = threadIdx.x;
    int tx = tid & 15, ty = tid >> 4;
    int tx4 = tx * 4;
    int rbase = blockIdx.x * 16;
    if (tid < 16) {
        int r = rbase + tid;
        invs[tid] = (r < n) ? 1.0f / RS[r] : 0.f;
    }
    __syncthreads();
    float acc[4] = {0.f, 0.f, 0.f, 0.f};

    for (int kb = 0; kb < n; kb += 64) {
        for (int i2 = tid; i2 < 1024; i2 += 256) {
            int rr = i2 >> 6, cc = i2 & 63;
            int gr = rbase + rr, gc = kb + cc;
            bool bit = (gr < n && gc < n) &&
                       ((CB[(size_t)gr * Wl + (gc >> 5)] >> (gc & 31)) & 1u);
            gs[rr][cc] = bit ? invs[rr] : 0.f;
        }
        for (int i2 = tid; i2 < 4096; i2 += 256) {
            int rr = i2 >> 6, cc = i2 & 63;
            int hr = kb + rr;
            hs[rr][cc] = (hr < n) ? h[(size_t)hr * DIMS + cc] : 0.f;
        }
        __syncthreads();
#pragma unroll 8
        for (int kk = 0; kk < 64; ++kk) {
            float a = gs[ty][kk];
            acc[0] = fmaf(a, hs[kk][tx4 + 0], acc[0]);
            acc[1] = fmaf(a, hs[kk][tx4 + 1], acc[1]);
            acc[2] = fmaf(a, hs[kk][tx4 + 2], acc[2]);
            acc[3] = fmaf(a, hs[kk][tx4 + 3], acc[3]);
        }
        __syncthreads();
    }
    int r = rbase + ty;
    if (r < n) {
#pragma unroll
        for (int j = 0; j < 4; ++j)
            t[(size_t)r * DIMS + tx4 + j] = acc[j];
    }
}

// ---- out = relu((t @ W) + b) [+ res]; 32 rows/block, W loaded once ----
__global__ void k_proj(const float* __restrict__ t, const float* __restrict__ Wm,
                       const float* __restrict__ b, const float* __restrict__ res,
                       float* __restrict__ out, int n) {
    __shared__ float Ws[64 * 64];
    __shared__ float Ts[4 * 64];
    int tid = threadIdx.x;
    int d = tid & 63;
    int r4 = tid >> 6;
    int rbase = blockIdx.x * 32;
    for (int i = tid; i < 4096; i += 256) Ws[i] = Wm[i];
    for (int pass = 0; pass < 8; ++pass) {
        int row = rbase + pass * 4 + r4;
        __syncthreads();
        Ts[tid] = (row < n) ? t[(size_t)row * DIMS + d] : 0.f;
        __syncthreads();
        if (row < n) {
            float acc = 0.f;
#pragma unroll
            for (int k = 0; k < 64; ++k)
                acc = fmaf(Ts[r4 * 64 + k], Ws[k * 64 + d], acc);
            acc = acc + b[d];
            acc = fmaxf(acc, 0.f);
            if (res) acc += res[(size_t)row * DIMS + d];
            out[(size_t)row * DIMS + d] = acc;
        }
    }
}

// ---- final proj: out2 = relu(tW+b)+res ; out3 = out2 + h_in ----
__global__ void k_proj_final(const float* __restrict__ t, const float* __restrict__ Wm,
                             const float* __restrict__ b, const float* __restrict__ res,
                             const float* __restrict__ hin,
                             float* __restrict__ out2, float* __restrict__ out3, int n) {
    __shared__ float Ws[64 * 64];
    __shared__ float Ts[4 * 64];
    int tid = threadIdx.x;
    int d = tid & 63;
    int r4 = tid >> 6;
    int rbase = blockIdx.x * 32;
    for (int i = tid; i < 4096; i += 256) Ws[i] = Wm[i];
    for (int pass = 0; pass < 8; ++pass) {
        int row = rbase + pass * 4 + r4;
        __syncthreads();
        Ts[tid] = (row < n) ? t[(size_t)row * DIMS + d] : 0.f;
        __syncthreads();
        if (row < n) {
            float acc = 0.f;
#pragma unroll
            for (int k = 0; k < 64; ++k)
                acc = fmaf(Ts[r4 * 64 + k], Ws[k * 64 + d], acc);
            acc = acc + b[d];
            acc = fmaxf(acc, 0.f);
            acc += res[(size_t)row * DIMS + d];
            out2[(size_t)row * DIMS + d] = acc;
            out3[(size_t)row * DIMS + d] = acc + hin[(size_t)row * DIMS + d];
        }
    }
}

// ---- scores -> packed sort keys: key = (~bits(sigmoid) << 32) | idx ----
__global__ void k_scores(const float* __restrict__ h, const float* __restrict__ pw,
                         const float* __restrict__ pb,
                         unsigned long long* __restrict__ keys, int n) {
    int warp = (int)((blockIdx.x * (unsigned)blockDim.x + threadIdx.x) >> 5);
    int lane = threadIdx.x & 31;
    if (warp >= SORTN) return;
    if (warp >= n) {
        if (lane == 0) keys[warp] = 0xFFFFFFFFFFFFFFFFull;
        return;
    }
    float acc = h[(size_t)warp * DIMS + lane] * pw[lane];
    acc = fmaf(h[(size_t)warp * DIMS + lane + 32], pw[lane + 32], acc);
#pragma unroll
    for (int off = 16; off > 0; off >>= 1) acc += __shfl_xor_sync(FULLMASK, acc, off);
    if (lane == 0) {
        unsigned fb = __float_as_uint(xla_sigmoidf(acc + pb[0]));
        keys[warp] = ((unsigned long long)(~fb) << 32) | (unsigned)warp;
    }
}

// ---- exact top-k by ranking: rank[i] = #{j: key[j] < key[i]} (keys unique) ----
__global__ void k_rank(const unsigned long long* __restrict__ keys, int k,
                       int* __restrict__ idx_out, float* __restrict__ vals_out) {
    int i = (int)((blockIdx.x * (unsigned)blockDim.x + threadIdx.x) >> 5);
    int lane = threadIdx.x & 31;
    if (i >= SORTN) return;
    unsigned long long ki = keys[i];
    int cnt = 0;
    for (int j = lane; j < SORTN; j += 32) cnt += (keys[j] < ki) ? 1 : 0;
#pragma unroll
    for (int off = 16; off > 0; off >>= 1) cnt += __shfl_xor_sync(FULLMASK, cnt, off);
    if (lane == 0 && cnt < k) {
        idx_out[cnt] = (int)(ki & 0xFFFFFFFFull);
        vals_out[cnt] = __uint_as_float(~(unsigned)(ki >> 32));
    }
}

// ---- hout[r] = hsrc[idx[r]] * vals[r]; 4 rows / 256-thread block ----
__global__ void k_gather(const float* __restrict__ hsrc, const int* __restrict__ idx,
                         const float* __restrict__ vals, float* __restrict__ hout, int rows) {
    int r = blockIdx.x * 4 + (threadIdx.x >> 6);
    int d = threadIdx.x & 63;
    if (r < rows)
        hout[(size_t)r * DIMS + d] = hsrc[(size_t)idx[r] * DIMS + d] * vals[r];
}

// ---- level-0 2-hop via row-OR over sparse neighbors; packed gathered output ----
__global__ void k_rowor(const unsigned* __restrict__ BITS0, const int* __restrict__ idx,
                        unsigned* __restrict__ CB1o, float* __restrict__ RS1o) {
    __shared__ unsigned own[W0];
    __shared__ unsigned accs[W0];
    __shared__ int cnt_sh;
    int i = blockIdx.x;
    int t = threadIdx.x;            // 128 threads
    own[t] = BITS0[(size_t)idx[i] * W0 + t];
    if (t == 0) cnt_sh = 0;
    __syncthreads();
    unsigned a = 0;
    for (int w2 = 0; w2 < W0; ++w2) {
        unsigned word = own[w2];
        while (word) {
            int c = (w2 << 5) + __ffs(word) - 1;
            word &= word - 1;
            a |= BITS0[(size_t)c * W0 + t];
        }
    }
    accs[t] = a;
    __syncthreads();
    int lane = t & 31, wp = t >> 5;  // 4 warps
    int cnt = 0;
    for (int ow = wp; ow < W1; ow += 4) {
        int j = (ow << 5) + lane;
        unsigned bit = 0;
        if (j < N1) {
            int col = idx[j];
            bit = (accs[col >> 5] >> (col & 31)) & 1u;
        }
        unsigned m = __ballot_sync(FULLMASK, bit);
        if (lane == 0) {
            CB1o[(size_t)i * W1 + ow] = m;
            cnt += __popc(m);
        }
    }
    if (lane == 0 && cnt) atomicAdd(&cnt_sh, cnt);
    __syncthreads();
    if (t == 0) RS1o[i] = (float)cnt_sh;
}

// ---- gather packed bit rows by idx ----
__global__ void k_packb(const unsigned* __restrict__ src, const int* __restrict__ idx,
                        unsigned* __restrict__ dst, int rows, int Wl) {
    int i = blockIdx.x * 256 + threadIdx.x;
    if (i >= rows * Wl) return;
    int r = i / Wl, w = i - r * Wl;
    dst[(size_t)r * Wl + w] = src[(size_t)idx[r] * Wl + w];
}

// ---- pairwise 2-hop with PACKED output (rowsum via k_count afterwards) ----
__global__ void k_pairb(const unsigned* __restrict__ A, int kk, int Wl, int Wout,
                        unsigned* __restrict__ CB) {
    __shared__ unsigned As[64 * 9];
    __shared__ unsigned Bs[64 * 9];
    __shared__ unsigned obits[128];
    int tid = threadIdx.x;
    int tx = tid & 15, ty = tid >> 4;
    int rbase = blockIdx.y * 64, cbase = blockIdx.x * 64;
    int ty4 = ty * 4, tx4 = tx * 4;
    if (tid < 128) obits[tid] = 0u;

    unsigned acc[4][4];
#pragma unroll
    for (int i = 0; i < 4; ++i)
#pragma unroll
        for (int j = 0; j < 4; ++j) {
            bool valid = (rbase + ty4 + i < kk) && (cbase + tx4 + j < kk);
            acc[i][j] = valid ? 0u : 1u;
        }

    bool done = false;
    for (int ch = 0; ch < Wl; ch += 8) {
        for (int i2 = tid; i2 < 512; i2 += 256) {
            int rr = i2 >> 3, ww = i2 & 7;
            int gw = ch + ww;
            int grow = rbase + rr;
            int gcol = cbase + rr;
            As[rr * 9 + ww] = (grow < kk && gw < Wl) ? A[(size_t)grow * Wl + gw] : 0u;
            Bs[rr * 9 + ww] = (gcol < kk && gw < Wl) ? A[(size_t)gcol * Wl + gw] : 0u;
        }
        __syncthreads();
        if (!done) {
#pragma unroll
            for (int w = 0; w < 8; ++w) {
                unsigned a0 = As[(ty4 + 0) * 9 + w];
                unsigned a1 = As[(ty4 + 1) * 9 + w];
                unsigned a2 = As[(ty4 + 2) * 9 + w];
                unsigned a3 = As[(ty4 + 3) * 9 + w];
                unsigned b0 = Bs[(tx4 + 0) * 9 + w];
                unsigned b1 = Bs[(tx4 + 1) * 9 + w];
                unsigned b2 = Bs[(tx4 + 2) * 9 + w];
                unsigned b3 = Bs[(tx4 + 3) * 9 + w];
                acc[0][0] |= a0 & b0; acc[0][1] |= a0 & b1; acc[0][2] |= a0 & b2; acc[0][3] |= a0 & b3;
                acc[1][0] |= a1 & b0; acc[1][1] |= a1 & b1; acc[1][2] |= a1 & b2; acc[1][3] |= a1 & b3;
                acc[2][0] |= a2 & b0; acc[2][1] |= a2 & b1; acc[2][2] |= a2 & b2; acc[2][3] |= a2 & b3;
                acc[3][0] |= a3 & b0; acc[3][1] |= a3 & b1; acc[3][2] |= a3 & b2; acc[3][3] |= a3 & b3;
            }
            bool d = true;
#pragma unroll
            for (int i = 0; i < 4; ++i)
#pragma unroll
                for (int j = 0; j < 4; ++j) d = d && (acc[i][j] != 0u);
            done = d;
        }
        if (__syncthreads_and(done ? 1 : 0)) break;
    }

    int word_half = tx >> 3;
    int shift = tx4 & 31;
#pragma unroll
    for (int i = 0; i < 4; ++i) {
        int r = rbase + ty4 + i;
        if (r < kk) {
            unsigned nib = 0;
#pragma unroll
            for (int j = 0; j < 4; ++j) {
                int c = cbase + tx4 + j;
                if (c < kk && acc[i][j]) nib |= (1u << j);
            }
            if (nib) atomicOr(&obits[(ty4 + i) * 2 + word_half], nib << shift);
        }
    }
    __syncthreads();
    if (tid < 128) {
        int rr = tid >> 1;
        int r = rbase + rr;
        int w = blockIdx.x * 2 + (tid & 1);
        if (r < kk && w < Wout) CB[(size_t)r * Wout + w] = obits[tid];
    }
}

__global__ void k_zero(float* __restrict__ p, int n) {
    int i = blockIdx.x * 256 + threadIdx.x;
    if (i < n) p[i] = 0.f;
}

__global__ void k_scatter(const float* __restrict__ hsrc, const int* __restrict__ idx,
                          float* __restrict__ u) {
    int b = blockIdx.x, t = threadIdx.x;
    u[(size_t)idx[b] * DIMS + t] = hsrc[(size_t)b * DIMS + t];
}

extern "C" void kernel_launch(void* const* d_in, const int* in_sizes, int n_in,
                              void* d_out, int out_size) {
    (void)in_sizes; (void)n_in; (void)out_size;
    const float* g0   = (const float*)d_in[0];
    const float* h_in = (const float*)d_in[1];
    const float* dW   = (const float*)d_in[2];
    const float* db   = (const float*)d_in[3];
    const float* uW   = (const float*)d_in[4];
    const float* ub   = (const float*)d_in[5];
    const float* pW   = (const float*)d_in[6];
    const float* pb   = (const float*)d_in[7];
    const float* bW   = (const float*)d_in[8];
    const float* bb   = (const float*)d_in[9];
    float* out = (float*)d_out;
    float* out0 = out;                               // [N2,64]
    float* out1 = out + (size_t)N2 * DIMS;           // [N1,64]
    float* out2 = out1 + (size_t)N1 * DIMS;          // [N0,64]
    float* out3 = out2 + (size_t)N0 * DIMS;          // [N0,64]

    void* basep = nullptr;
    cudaGetSymbolAddress(&basep, g_arena);
    char* base = (char*)basep;
    unsigned* CB0  = (unsigned*)(base + A_CB0);
    unsigned* CB1  = (unsigned*)(base + A_CB1);
    unsigned* CB2  = (unsigned*)(base + A_CB2);
    unsigned* CB3  = (unsigned*)(base + A_CB3);
    unsigned* BITS = (unsigned*)(base + A_BITS);
    float*    T    = (float*)(base + A_T);
    float*    U    = (float*)(base + A_U);
    float*    Hb   = (float*)(base + A_H);
    float*    D0b  = (float*)(base + A_D0);
    float*    D1b  = (float*)(base + A_D1);
    float*    D2b  = (float*)(base + A_D2);
    unsigned long long* KEYS = (unsigned long long*)(base + A_KEYS);
    float*    SV   = (float*)(base + A_SV);
    int*      I0   = (int*)(base + A_I0);
    int*      I1   = (int*)(base + A_I1);
    int*      I2   = (int*)(base + A_I2);
    float*    RS0  = (float*)(base + A_RS0);
    float*    RS1  = (float*)(base + A_RS1);
    float*    RS2  = (float*)(base + A_RS2);
    float*    RS3  = (float*)(base + A_RS3);

    // ---------------- down level 0 ----------------
    k_packcnt<<<N0, 256>>>(g0, CB0, RS0, N0, W0);
    k_spmm_bits<<<(N0 + 7) / 8, 256>>>(CB0, RS0, h_in, T, N0, W0);
    k_proj<<<(N0 + 31) / 32, 256>>>(T, dW, db, nullptr, D0b, N0);
    k_scores<<<SORTN / 8, 256>>>(D0b, pW, pb, KEYS, N0);
    k_rank<<<SORTN / 8, 256>>>(KEYS, N1, I0, SV);
    k_gather<<<(N1 + 3) / 4, 256>>>(D0b, I0, SV, Hb, N1);
    k_rowor<<<N1, 128>>>(CB0, I0, CB1, RS1);

    // ---------------- down level 1 ----------------
    k_spmm_bits<<<(N1 + 7) / 8, 256>>>(CB1, RS1, Hb, T, N1, W1);
    k_proj<<<(N1 + 31) / 32, 256>>>(T, dW + 4096, db + 64, nullptr, D1b, N1);
    k_scores<<<SORTN / 8, 256>>>(D1b, pW + 64, pb + 1, KEYS, N1);
    k_rank<<<SORTN / 8, 256>>>(KEYS, N2, I1, SV);
    k_gather<<<(N2 + 3) / 4, 256>>>(D1b, I1, SV, Hb, N2);
    k_packb<<<(N2 * W1 + 255) / 256, 256>>>(CB1, I1, BITS, N2, W1);
    {
        dim3 grid((N2 + 63) / 64, (N2 + 63) / 64);
        k_pairb<<<grid, 256>>>(BITS, N2, W1, W2, CB2);
    }
    k_count<<<(N2 + 7) / 8, 256>>>(CB2, RS2, N2, W2);

    // ---------------- down level 2 ----------------
    k_gemm_bits<<<(N2 + 15) / 16, 256>>>(CB2, RS2, Hb, T, N2, W2);
    k_proj<<<(N2 + 31) / 32, 256>>>(T, dW + 8192, db + 128, nullptr, D2b, N2);
    k_scores<<<SORTN / 8, 256>>>(D2b, pW + 128, pb + 2, KEYS, N2);
    k_rank<<<SORTN / 8, 256>>>(KEYS, N3, I2, SV);
    k_gather<<<(N3 + 3) / 4, 256>>>(D2b, I2, SV, Hb, N3);
    k_packb<<<(N3 * W2 + 255) / 256, 256>>>(CB2, I2, BITS, N3, W2);
    {
        dim3 grid((N3 + 63) / 64, (N3 + 63) / 64);
        k_pairb<<<grid, 256>>>(BITS, N3, W2, W3, CB3);
    }
    k_count<<<(N3 + 7) / 8, 256>>>(CB3, RS3, N3, W3);

    // ---------------- bottom ----------------
    k_gemm_bits<<<(N3 + 15) / 16, 256>>>(CB3, RS3, Hb, T, N3, W3);
    k_proj<<<(N3 + 31) / 32, 256>>>(T, bW, bb, nullptr, Hb, N3);

    // ---------------- up level 0 (uses CB2, I2) ----------------
    k_zero<<<(N2 * DIMS + 255) / 256, 256>>>(U, N2 * DIMS);
    k_scatter<<<N3, 64>>>(Hb, I2, U);
    k_gemm_bits<<<(N2 + 15) / 16, 256>>>(CB2, RS2, U, T, N2, W2);
    k_proj<<<(N2 + 31) / 32, 256>>>(T, uW, ub, D2b, out0, N2);

    // ---------------- up level 1 (uses CB1, I1) ----------------
    k_zero<<<(N1 * DIMS + 255) / 256, 256>>>(U, N1 * DIMS);
    k_scatter<<<N2, 64>>>(out0, I1, U);
    k_spmm_bits<<<(N1 + 7) / 8, 256>>>(CB1, RS1, U, T, N1, W1);
    k_proj<<<(N1 + 31) / 32, 256>>>(T, uW + 4096, ub + 64, D1b, out1, N1);

    // ---------------- up level 2 (uses CB0, I0) ----------------
    k_zero<<<(N0 * DIMS + 255) / 256, 256>>>(U, N0 * DIMS);
    k_scatter<<<N1, 64>>>(out1, I0, U);
    k_spmm_bits<<<(N0 + 7) / 8, 256>>>(CB0, RS0, U, T, N0, W0);
    k_proj_final<<<(N0 + 31) / 32, 256>>>(T, uW + 8192, ub + 128, D0b, h_in, out2, out3, N0);
}